// round 3
// baseline (speedup 1.0000x reference)
#include <cuda_runtime.h>
#include <cuda_bf16.h>
#include <math.h>

#define BATCH 4
#define IMH 64
#define IMW 64
#define CDIM 128
#define NPIX (BATCH * IMH * IMW)   // 16384
#define NHEADS 4
#define HD 32
#define NBK 7
#define HID 512

// Scratch (device globals — no allocation allowed)
__device__ float g_xn[NPIX * CDIM];
__device__ float g_qkv[NPIX * 3 * CDIM];
__device__ float g_scores[BATCH * IMH * NHEADS * NBK * IMW]; // [b,y,h,ky,nx]
__device__ float g_attn[NPIX * CDIM];
__device__ float g_h[NPIX * CDIM];
__device__ float g_y[NPIX * CDIM];
__device__ float g_mlp[NPIX * HID];

// ---------------------------------------------------------------------------
// LayerNorm: one block per row (128 threads, 1 elem/thread)
// ---------------------------------------------------------------------------
__global__ void ln_kernel(const float* __restrict__ x,
                          const float* __restrict__ gamma,
                          const float* __restrict__ beta,
                          float* __restrict__ out) {
    int row = blockIdx.x;
    int t = threadIdx.x;
    float v = x[row * CDIM + t];

    __shared__ float s1[4], s2[4];
    int lane = t & 31, warp = t >> 5;

    float ws = v;
    #pragma unroll
    for (int off = 16; off; off >>= 1) ws += __shfl_xor_sync(0xffffffffu, ws, off);
    if (lane == 0) s1[warp] = ws;
    __syncthreads();
    float mean = (s1[0] + s1[1] + s1[2] + s1[3]) * (1.0f / CDIM);

    float d = v - mean;
    float ws2 = d * d;
    #pragma unroll
    for (int off = 16; off; off >>= 1) ws2 += __shfl_xor_sync(0xffffffffu, ws2, off);
    if (lane == 0) s2[warp] = ws2;
    __syncthreads();
    float var = (s2[0] + s2[1] + s2[2] + s2[3]) * (1.0f / CDIM);

    out[row * CDIM + t] = d * rsqrtf(var + 1e-5f) * gamma[t] + beta[t];
}

// ---------------------------------------------------------------------------
// Tiled fp32 GEMM: C = A @ B + bias (+res) (+gelu).  BM=BN=64, BK=16.
// ---------------------------------------------------------------------------
#define BM 64
#define BN 64
#define BKT 16

__global__ void gemm_kernel(const float* __restrict__ A,
                            const float* __restrict__ B,
                            const float* __restrict__ bias,
                            const float* __restrict__ res,
                            float* __restrict__ C,
                            int M, int N, int Kdim, int epi) {
    __shared__ float As[BKT][BM];
    __shared__ float Bs[BKT][BN];

    int tid = threadIdx.x;
    int tx = tid & 15;
    int ty = tid >> 4;
    int aRow0 = blockIdx.y * BM;
    int bCol0 = blockIdx.x * BN;

    float acc[4][4] = {};

    for (int k0 = 0; k0 < Kdim; k0 += BKT) {
        #pragma unroll
        for (int j = 0; j < 4; j++) {
            int i = tid + j * 256;
            int r = i >> 4, c = i & 15;
            As[c][r] = A[(aRow0 + r) * Kdim + k0 + c];
        }
        #pragma unroll
        for (int j = 0; j < 4; j++) {
            int i = tid + j * 256;
            int r = i >> 6, c = i & 63;
            Bs[r][c] = B[(k0 + r) * N + bCol0 + c];
        }
        __syncthreads();

        #pragma unroll
        for (int kk = 0; kk < BKT; kk++) {
            float4 ra = *reinterpret_cast<const float4*>(&As[kk][ty * 4]);
            float4 rb = *reinterpret_cast<const float4*>(&Bs[kk][tx * 4]);
            float a0[4] = {ra.x, ra.y, ra.z, ra.w};
            float b0[4] = {rb.x, rb.y, rb.z, rb.w};
            #pragma unroll
            for (int i = 0; i < 4; i++)
                #pragma unroll
                for (int j = 0; j < 4; j++)
                    acc[i][j] = fmaf(a0[i], b0[j], acc[i][j]);
        }
        __syncthreads();
    }

    int colBase = bCol0 + tx * 4;
    float4 bv = *reinterpret_cast<const float4*>(&bias[colBase]);
    #pragma unroll
    for (int i = 0; i < 4; i++) {
        int row = aRow0 + ty * 4 + i;
        float v[4] = {acc[i][0] + bv.x, acc[i][1] + bv.y,
                      acc[i][2] + bv.z, acc[i][3] + bv.w};
        if (epi == 1) {
            float4 rv = *reinterpret_cast<const float4*>(&res[row * N + colBase]);
            v[0] += rv.x; v[1] += rv.y; v[2] += rv.z; v[3] += rv.w;
        } else if (epi == 2) {
            #pragma unroll
            for (int j = 0; j < 4; j++)
                v[j] = 0.5f * v[j] * (1.0f + erff(v[j] * 0.7071067811865476f));
        }
        float4 ov = {v[0], v[1], v[2], v[3]};
        *reinterpret_cast<float4*>(&C[row * N + colBase]) = ov;
    }
}

// ---------------------------------------------------------------------------
// Scores: per (b,y): qsum[c] = scale * sum_x q[b,y,x,c]  (reference einsum
// contracts q over the W axis!), then dot[h,ky,nx] = qsum_h . k[b,sy+ky,nx,h].
// Block = one (b,y), 256 threads. Dots: 8 lanes per dot, 4 dots per warp-iter.
// ---------------------------------------------------------------------------
__global__ void score_kernel(const float* __restrict__ qkv,
                             float* __restrict__ scores) {
    int by = blockIdx.x;           // b*64 + y
    int b = by >> 6, y = by & 63;
    int t = threadIdx.x;

    __shared__ float qp[2][CDIM];
    __shared__ float qs[CDIM];

    int c = t & 127, half = t >> 7;
    float s = 0.0f;
    long rowbase = (long)(by * 64) * 384;
    #pragma unroll 4
    for (int x = half * 32; x < half * 32 + 32; x++)
        s += qkv[rowbase + x * 384 + c];
    qp[half][c] = s;
    __syncthreads();
    if (t < 128) qs[t] = (qp[0][t] + qp[1][t]) * 0.17677669529663687f;
    __syncthreads();

    int sy = min(max(y - 3, 0), IMH - NBK);
    int lane = t & 31, wi = t >> 5;
    int g = lane >> 3;       // dot group within warp (4 dots/iter)
    int l = lane & 7;        // 8 lanes per dot, 4 c-elems each

    for (int tt = 0; tt < 56; tt++) {
        int d = wi * 224 + tt * 4 + g;        // d in [0,1792): h*448+ky*64+nx
        int h = d / 448, rem = d % 448;
        int ky = rem >> 6, nx = rem & 63;
        int np = (b * 64 + sy + ky) * 64 + nx;
        float4 kk = *reinterpret_cast<const float4*>(
            &qkv[(long)np * 384 + CDIM + h * HD + l * 4]);
        float4 qq = *reinterpret_cast<const float4*>(&qs[h * HD + l * 4]);
        float val = kk.x * qq.x + kk.y * qq.y + kk.z * qq.z + kk.w * qq.w;
        #pragma unroll
        for (int off = 4; off; off >>= 1)
            val += __shfl_xor_sync(0xffffffffu, val, off);
        if (l == 0) scores[(long)by * 1792 + d] = val;
    }
}

// ---------------------------------------------------------------------------
// AV: per pixel block (128 threads), warp = head. Read 49 scores, add rpb,
// softmax, weighted sum over v neighborhood.
// ---------------------------------------------------------------------------
__global__ void attn_av_kernel(const float* __restrict__ qkv,
                               const float* __restrict__ scores,
                               const float* __restrict__ rpb,
                               float* __restrict__ out) {
    int p = blockIdx.x;
    int b = p >> 12, y = (p >> 6) & 63, x = p & 63;
    int h = threadIdx.x >> 5, lane = threadIdx.x & 31;

    int sy = min(max(y - 3, 0), IMH - NBK);
    int sx = min(max(x - 3, 0), IMW - NBK);
    const float* srow = scores + ((long)((b * 64 + y) * NHEADS + h)) * (NBK * 64);

    __shared__ float sc[NHEADS][NBK * NBK];

    float s0, s1 = -1e30f;
    {
        int n = lane;                        // lane < 32 <= 48
        int ky = n / NBK, kx = n - ky * NBK;
        float bias = rpb[(h * 13 + (sy + ky - y + 6)) * 13 + (sx + kx - x + 6)];
        s0 = srow[ky * 64 + sx + kx] + bias;
    }
    if (lane < 17) {
        int n = lane + 32;
        int ky = n / NBK, kx = n - ky * NBK;
        float bias = rpb[(h * 13 + (sy + ky - y + 6)) * 13 + (sx + kx - x + 6)];
        s1 = srow[ky * 64 + sx + kx] + bias;
    }
    float m = fmaxf(s0, s1);
    #pragma unroll
    for (int off = 16; off; off >>= 1)
        m = fmaxf(m, __shfl_xor_sync(0xffffffffu, m, off));
    float e0 = __expf(s0 - m);
    float e1 = (lane < 17) ? __expf(s1 - m) : 0.0f;
    float sum = e0 + e1;
    #pragma unroll
    for (int off = 16; off; off >>= 1)
        sum += __shfl_xor_sync(0xffffffffu, sum, off);
    sc[h][lane] = e0;
    if (lane < 17) sc[h][lane + 32] = e1;
    __syncwarp();
    float inv = 1.0f / sum;

    float acc = 0.0f;
    #pragma unroll 7
    for (int n = 0; n < NBK * NBK; n++) {
        int ky = n / NBK, kx = n - ky * NBK;
        int np = (b * 64 + sy + ky) * 64 + sx + kx;
        acc = fmaf(sc[h][n], qkv[(long)np * 384 + 2 * CDIM + h * HD + lane], acc);
    }
    out[(long)p * CDIM + h * HD + lane] = acc * inv;
}

// ---------------------------------------------------------------------------
extern "C" void kernel_launch(void* const* d_in, const int* in_sizes, int n_in,
                              void* d_out, int out_size) {
    const float* x      = (const float*)d_in[0];
    const float* ln1_g  = (const float*)d_in[1];
    const float* ln1_b  = (const float*)d_in[2];
    const float* qkv_w  = (const float*)d_in[3];
    const float* qkv_b  = (const float*)d_in[4];
    const float* rpb    = (const float*)d_in[5];
    const float* proj_w = (const float*)d_in[6];
    const float* proj_b = (const float*)d_in[7];
    const float* ln2_g  = (const float*)d_in[8];
    const float* ln2_b  = (const float*)d_in[9];
    const float* fc1_w  = (const float*)d_in[10];
    const float* fc1_b  = (const float*)d_in[11];
    const float* fc2_w  = (const float*)d_in[12];
    const float* fc2_b  = (const float*)d_in[13];
    float* out = (float*)d_out;

    float *xn, *qkvb, *scoresb, *attnb, *hb, *yb, *mlpb;
    cudaGetSymbolAddress((void**)&xn,      g_xn);
    cudaGetSymbolAddress((void**)&qkvb,    g_qkv);
    cudaGetSymbolAddress((void**)&scoresb, g_scores);
    cudaGetSymbolAddress((void**)&attnb,   g_attn);
    cudaGetSymbolAddress((void**)&hb,      g_h);
    cudaGetSymbolAddress((void**)&yb,      g_y);
    cudaGetSymbolAddress((void**)&mlpb,    g_mlp);

    // 1. LN1
    ln_kernel<<<NPIX, CDIM>>>(x, ln1_g, ln1_b, xn);
    // 2. QKV GEMM
    gemm_kernel<<<dim3(384 / BN, NPIX / BM), 256>>>(xn, qkv_w, qkv_b, nullptr,
                                                    qkvb, NPIX, 384, CDIM, 0);
    // 3a. Row-summed-query scores
    score_kernel<<<BATCH * IMH, 256>>>(qkvb, scoresb);
    // 3b. Softmax + AV
    attn_av_kernel<<<NPIX, 128>>>(qkvb, scoresb, rpb, attnb);
    // 4. Proj GEMM + residual(x)
    gemm_kernel<<<dim3(CDIM / BN, NPIX / BM), 256>>>(attnb, proj_w, proj_b, x,
                                                     hb, NPIX, CDIM, CDIM, 1);
    // 5. LN2
    ln_kernel<<<NPIX, CDIM>>>(hb, ln2_g, ln2_b, yb);
    // 6. FC1 GEMM + GELU
    gemm_kernel<<<dim3(HID / BN, NPIX / BM), 256>>>(yb, fc1_w, fc1_b, nullptr,
                                                    mlpb, NPIX, HID, CDIM, 2);
    // 7. FC2 GEMM + residual(h)
    gemm_kernel<<<dim3(CDIM / BN, NPIX / BM), 256>>>(mlpb, fc2_w, fc2_b, hb,
                                                     out, NPIX, CDIM, HID, 1);
}

// round 6
// speedup vs baseline: 1.6495x; 1.6495x over previous
#include <cuda_runtime.h>
#include <cuda_bf16.h>
#include <math.h>
#include <stdint.h>

#define BATCH 4
#define IMH 64
#define IMW 64
#define CDIM 128
#define NPIX (BATCH * IMH * IMW)   // 16384
#define NHEADS 4
#define HD 32
#define NBK 7
#define HID 512

// Scratch (device globals — no allocation allowed)
__device__ float g_xn[NPIX * CDIM];
__device__ float g_qkv[NPIX * 3 * CDIM];
__device__ float g_scores[BATCH * IMH * NHEADS * NBK * IMW];
__device__ float g_attn[NPIX * CDIM];
__device__ float g_h[NPIX * CDIM];
__device__ float g_y[NPIX * CDIM];
__device__ float g_mlp[NPIX * HID];
// bf16 transposed weights: BT[n][k] = W[k][n]
__device__ __nv_bfloat16 g_wqkvT[384 * 128];
__device__ __nv_bfloat16 g_wprojT[128 * 128];
__device__ __nv_bfloat16 g_wfc1T[512 * 128];
__device__ __nv_bfloat16 g_wfc2T[128 * 512];

// ---------------------------------------------------------------------------
// mma.sync helpers (compute_103-safe; no tcgen05)
// ---------------------------------------------------------------------------
__device__ __forceinline__ uint32_t smem_u32(const void* p) {
    uint32_t a;
    asm("{ .reg .u64 t; cvta.to.shared.u64 t, %1; cvt.u32.u64 %0, t; }"
        : "=r"(a) : "l"(p));
    return a;
}
__device__ __forceinline__ void ldm_x4(uint32_t* r, uint32_t addr) {
    asm volatile("ldmatrix.sync.aligned.m8n8.x4.shared.b16 {%0,%1,%2,%3}, [%4];"
                 : "=r"(r[0]), "=r"(r[1]), "=r"(r[2]), "=r"(r[3]) : "r"(addr));
}
__device__ __forceinline__ void ldm_x2(uint32_t* r, uint32_t addr) {
    asm volatile("ldmatrix.sync.aligned.m8n8.x2.shared.b16 {%0,%1}, [%2];"
                 : "=r"(r[0]), "=r"(r[1]) : "r"(addr));
}
__device__ __forceinline__ void mma_bf16(float* c, const uint32_t* a,
                                         const uint32_t* b) {
    asm volatile(
        "mma.sync.aligned.m16n8k16.row.col.f32.bf16.bf16.f32 "
        "{%0,%1,%2,%3}, {%4,%5,%6,%7}, {%8,%9}, {%0,%1,%2,%3};"
        : "+f"(c[0]), "+f"(c[1]), "+f"(c[2]), "+f"(c[3])
        : "r"(a[0]), "r"(a[1]), "r"(a[2]), "r"(a[3]), "r"(b[0]), "r"(b[1]));
}

// ---------------------------------------------------------------------------
// Weight prep: transpose + convert to bf16, BT[n][k] = W[k][n]
// ---------------------------------------------------------------------------
__global__ void prep_w_kernel(const float* __restrict__ qkv_w,
                              const float* __restrict__ proj_w,
                              const float* __restrict__ fc1_w,
                              const float* __restrict__ fc2_w) {
    int t = blockIdx.x * blockDim.x + threadIdx.x;
    if (t < 49152) {
        int n = t / 128, k = t % 128;
        g_wqkvT[t] = __float2bfloat16(qkv_w[k * 384 + n]);
        return;
    }
    t -= 49152;
    if (t < 16384) {
        int n = t / 128, k = t % 128;
        g_wprojT[t] = __float2bfloat16(proj_w[k * 128 + n]);
        return;
    }
    t -= 16384;
    if (t < 65536) {
        int n = t / 128, k = t % 128;
        g_wfc1T[t] = __float2bfloat16(fc1_w[k * 512 + n]);
        return;
    }
    t -= 65536;
    if (t < 65536) {
        int n = t / 512, k = t % 512;
        g_wfc2T[t] = __float2bfloat16(fc2_w[k * 128 + n]);
    }
}

// ---------------------------------------------------------------------------
// bf16 mma.sync GEMM: C[M,N] = A[M,K] @ BT[N,K]^T + bias (+res | +gelu)
// Block 64x128, BK=32, 256 threads (8 warps: 2 M x 4 N), warp tile 32x32.
// epi: 0=bias, 1=bias+res, 2=bias+gelu
// ---------------------------------------------------------------------------
#define BMT 64
#define BNT 128
#define BKT 32
#define PADT 8
#define ASTR (BKT + PADT)   // 40 bf16 = 80B row stride

__global__ void mma_gemm_kernel(const float* __restrict__ A,
                                const __nv_bfloat16* __restrict__ BT,
                                const float* __restrict__ bias,
                                const float* __restrict__ res,
                                float* __restrict__ C,
                                int N, int Kdim, int epi) {
    __shared__ __nv_bfloat16 As[BMT][ASTR];
    __shared__ __nv_bfloat16 Bs[BNT][ASTR];

    int tid = threadIdx.x;
    int wid = tid >> 5, lane = tid & 31;
    int warp_m = wid >> 2;          // 0..1
    int warp_n = wid & 3;           // 0..3
    int m0 = blockIdx.y * BMT;
    int n0 = blockIdx.x * BNT;

    float acc[2][4][4] = {};

    // Precompute ldmatrix SMEM addresses (row/col pattern is loop-invariant)
    // A: row = warp_m*32 + mtile*16 + (lane&15), col = ks*16 + (lane>>4)*8
    uint32_t aAddr[2];   // per mtile, base for ks=0
    #pragma unroll
    for (int mt = 0; mt < 2; mt++)
        aAddr[mt] = smem_u32(&As[warp_m * 32 + mt * 16 + (lane & 15)][(lane >> 4) * 8]);
    // B: row = warp_n*32 + ntile*8 + (lane&7), col = ks*16 + ((lane>>3)&1)*8
    uint32_t bAddr[4];
    #pragma unroll
    for (int nt = 0; nt < 4; nt++)
        bAddr[nt] = smem_u32(&Bs[warp_n * 32 + nt * 8 + (lane & 7)][((lane >> 3) & 1) * 8]);

    for (int kc = 0; kc < Kdim; kc += BKT) {
        // Load A tile 64x32 fp32 -> bf16 (512 float4, 2/thread)
        #pragma unroll
        for (int j = 0; j < 2; j++) {
            int idx = tid + j * 256;
            int r = idx >> 3, c4 = idx & 7;
            float4 v = *reinterpret_cast<const float4*>(
                &A[(long)(m0 + r) * Kdim + kc + c4 * 4]);
            __nv_bfloat162 p0 = __float22bfloat162_rn(make_float2(v.x, v.y));
            __nv_bfloat162 p1 = __float22bfloat162_rn(make_float2(v.z, v.w));
            uint2 u;
            u.x = *reinterpret_cast<uint32_t*>(&p0);
            u.y = *reinterpret_cast<uint32_t*>(&p1);
            *reinterpret_cast<uint2*>(&As[r][c4 * 4]) = u;
        }
        // Load B tile 128x32 bf16 (512 uint4, 2/thread)
        #pragma unroll
        for (int j = 0; j < 2; j++) {
            int idx = tid + j * 256;
            int r = idx >> 2, c8 = idx & 3;
            uint4 u = *reinterpret_cast<const uint4*>(
                &BT[(long)(n0 + r) * Kdim + kc + c8 * 8]);
            *reinterpret_cast<uint4*>(&Bs[r][c8 * 8]) = u;
        }
        __syncthreads();

        #pragma unroll
        for (int ks = 0; ks < 2; ks++) {
            uint32_t af[2][4], bf[4][2];
            #pragma unroll
            for (int mt = 0; mt < 2; mt++)
                ldm_x4(af[mt], aAddr[mt] + ks * 32);   // +16 bf16 cols = 32B
            #pragma unroll
            for (int nt = 0; nt < 4; nt++)
                ldm_x2(bf[nt], bAddr[nt] + ks * 32);
            #pragma unroll
            for (int mt = 0; mt < 2; mt++)
                #pragma unroll
                for (int nt = 0; nt < 4; nt++)
                    mma_bf16(acc[mt][nt], af[mt], bf[nt]);
        }
        __syncthreads();
    }

    // Epilogue: per fragment, thread t: c0,c1 -> (row, col..col+1), c2,c3 -> row+8
    int trow = lane >> 2, tcol = (lane & 3) * 2;
    #pragma unroll
    for (int mt = 0; mt < 2; mt++) {
        #pragma unroll
        for (int nt = 0; nt < 4; nt++) {
            int col = n0 + warp_n * 32 + nt * 8 + tcol;
            float b0 = bias[col], b1 = bias[col + 1];
            #pragma unroll
            for (int hh = 0; hh < 2; hh++) {
                int row = m0 + warp_m * 32 + mt * 16 + trow + hh * 8;
                float v0 = acc[mt][nt][hh * 2 + 0] + b0;
                float v1 = acc[mt][nt][hh * 2 + 1] + b1;
                if (epi == 1) {
                    float2 rv = *reinterpret_cast<const float2*>(
                        &res[(long)row * N + col]);
                    v0 += rv.x; v1 += rv.y;
                } else if (epi == 2) {
                    v0 = 0.5f * v0 * (1.0f + erff(v0 * 0.7071067811865476f));
                    v1 = 0.5f * v1 * (1.0f + erff(v1 * 0.7071067811865476f));
                }
                float2 ov = {v0, v1};
                *reinterpret_cast<float2*>(&C[(long)row * N + col]) = ov;
            }
        }
    }
}

// ---------------------------------------------------------------------------
// LayerNorm
// ---------------------------------------------------------------------------
__global__ void ln_kernel(const float* __restrict__ x,
                          const float* __restrict__ gamma,
                          const float* __restrict__ beta,
                          float* __restrict__ out) {
    int row = blockIdx.x;
    int t = threadIdx.x;
    float v = x[row * CDIM + t];

    __shared__ float s1[4], s2[4];
    int lane = t & 31, warp = t >> 5;

    float ws = v;
    #pragma unroll
    for (int off = 16; off; off >>= 1) ws += __shfl_xor_sync(0xffffffffu, ws, off);
    if (lane == 0) s1[warp] = ws;
    __syncthreads();
    float mean = (s1[0] + s1[1] + s1[2] + s1[3]) * (1.0f / CDIM);

    float d = v - mean;
    float ws2 = d * d;
    #pragma unroll
    for (int off = 16; off; off >>= 1) ws2 += __shfl_xor_sync(0xffffffffu, ws2, off);
    if (lane == 0) s2[warp] = ws2;
    __syncthreads();
    float var = (s2[0] + s2[1] + s2[2] + s2[3]) * (1.0f / CDIM);

    out[row * CDIM + t] = d * rsqrtf(var + 1e-5f) * gamma[t] + beta[t];
}

// ---------------------------------------------------------------------------
// Scores (row-summed query — reference einsum contracts q over W axis)
// ---------------------------------------------------------------------------
__global__ void score_kernel(const float* __restrict__ qkv,
                             float* __restrict__ scores) {
    int by = blockIdx.x;
    int b = by >> 6, y = by & 63;
    int t = threadIdx.x;

    __shared__ float qp[2][CDIM];
    __shared__ float qs[CDIM];

    int c = t & 127, half = t >> 7;
    float s = 0.0f;
    long rowbase = (long)(by * 64) * 384;
    #pragma unroll 4
    for (int x = half * 32; x < half * 32 + 32; x++)
        s += qkv[rowbase + x * 384 + c];
    qp[half][c] = s;
    __syncthreads();
    if (t < 128) qs[t] = (qp[0][t] + qp[1][t]) * 0.17677669529663687f;
    __syncthreads();

    int sy = min(max(y - 3, 0), IMH - NBK);
    int lane = t & 31, wi = t >> 5;
    int g = lane >> 3;
    int l = lane & 7;

    for (int tt = 0; tt < 56; tt++) {
        int d = wi * 224 + tt * 4 + g;
        int h = d / 448, rem = d % 448;
        int ky = rem >> 6, nx = rem & 63;
        int np = (b * 64 + sy + ky) * 64 + nx;
        float4 kk = *reinterpret_cast<const float4*>(
            &qkv[(long)np * 384 + CDIM + h * HD + l * 4]);
        float4 qq = *reinterpret_cast<const float4*>(&qs[h * HD + l * 4]);
        float val = kk.x * qq.x + kk.y * qq.y + kk.z * qq.z + kk.w * qq.w;
        #pragma unroll
        for (int off = 4; off; off >>= 1)
            val += __shfl_xor_sync(0xffffffffu, val, off);
        if (l == 0) scores[(long)by * 1792 + d] = val;
    }
}

// ---------------------------------------------------------------------------
// Softmax + AV
// ---------------------------------------------------------------------------
__global__ void attn_av_kernel(const float* __restrict__ qkv,
                               const float* __restrict__ scores,
                               const float* __restrict__ rpb,
                               float* __restrict__ out) {
    int p = blockIdx.x;
    int b = p >> 12, y = (p >> 6) & 63, x = p & 63;
    int h = threadIdx.x >> 5, lane = threadIdx.x & 31;

    int sy = min(max(y - 3, 0), IMH - NBK);
    int sx = min(max(x - 3, 0), IMW - NBK);
    const float* srow = scores + ((long)((b * 64 + y) * NHEADS + h)) * (NBK * 64);

    __shared__ float sc[NHEADS][NBK * NBK];

    float s0, s1 = -1e30f;
    {
        int n = lane;
        int ky = n / NBK, kx = n - ky * NBK;
        float bias = rpb[(h * 13 + (sy + ky - y + 6)) * 13 + (sx + kx - x + 6)];
        s0 = srow[ky * 64 + sx + kx] + bias;
    }
    if (lane < 17) {
        int n = lane + 32;
        int ky = n / NBK, kx = n - ky * NBK;
        float bias = rpb[(h * 13 + (sy + ky - y + 6)) * 13 + (sx + kx - x + 6)];
        s1 = srow[ky * 64 + sx + kx] + bias;
    }
    float m = fmaxf(s0, s1);
    #pragma unroll
    for (int off = 16; off; off >>= 1)
        m = fmaxf(m, __shfl_xor_sync(0xffffffffu, m, off));
    float e0 = __expf(s0 - m);
    float e1 = (lane < 17) ? __expf(s1 - m) : 0.0f;
    float sum = e0 + e1;
    #pragma unroll
    for (int off = 16; off; off >>= 1)
        sum += __shfl_xor_sync(0xffffffffu, sum, off);
    sc[h][lane] = e0;
    if (lane < 17) sc[h][lane + 32] = e1;
    __syncwarp();
    float inv = 1.0f / sum;

    float acc = 0.0f;
    #pragma unroll 7
    for (int n = 0; n < NBK * NBK; n++) {
        int ky = n / NBK, kx = n - ky * NBK;
        int np = (b * 64 + sy + ky) * 64 + sx + kx;
        acc = fmaf(sc[h][n], qkv[(long)np * 384 + 2 * CDIM + h * HD + lane], acc);
    }
    out[(long)p * CDIM + h * HD + lane] = acc * inv;
}

// ---------------------------------------------------------------------------
extern "C" void kernel_launch(void* const* d_in, const int* in_sizes, int n_in,
                              void* d_out, int out_size) {
    const float* x      = (const float*)d_in[0];
    const float* ln1_g  = (const float*)d_in[1];
    const float* ln1_b  = (const float*)d_in[2];
    const float* qkv_w  = (const float*)d_in[3];
    const float* qkv_b  = (const float*)d_in[4];
    const float* rpb    = (const float*)d_in[5];
    const float* proj_w = (const float*)d_in[6];
    const float* proj_b = (const float*)d_in[7];
    const float* ln2_g  = (const float*)d_in[8];
    const float* ln2_b  = (const float*)d_in[9];
    const float* fc1_w  = (const float*)d_in[10];
    const float* fc1_b  = (const float*)d_in[11];
    const float* fc2_w  = (const float*)d_in[12];
    const float* fc2_b  = (const float*)d_in[13];
    float* out = (float*)d_out;

    float *xn, *qkvb, *scoresb, *attnb, *hb, *yb, *mlpb;
    cudaGetSymbolAddress((void**)&xn,      g_xn);
    cudaGetSymbolAddress((void**)&qkvb,    g_qkv);
    cudaGetSymbolAddress((void**)&scoresb, g_scores);
    cudaGetSymbolAddress((void**)&attnb,   g_attn);
    cudaGetSymbolAddress((void**)&hb,      g_h);
    cudaGetSymbolAddress((void**)&yb,      g_y);
    cudaGetSymbolAddress((void**)&mlpb,    g_mlp);
    __nv_bfloat16 *wqkvT, *wprojT, *wfc1T, *wfc2T;
    cudaGetSymbolAddress((void**)&wqkvT, g_wqkvT);
    cudaGetSymbolAddress((void**)&wprojT, g_wprojT);
    cudaGetSymbolAddress((void**)&wfc1T, g_wfc1T);
    cudaGetSymbolAddress((void**)&wfc2T, g_wfc2T);

    // 0. Weight prep (transpose + bf16)
    prep_w_kernel<<<768, 256>>>(qkv_w, proj_w, fc1_w, fc2_w);
    // 1. LN1
    ln_kernel<<<NPIX, CDIM>>>(x, ln1_g, ln1_b, xn);
    // 2. QKV GEMM [16384,128]x[128,384]
    mma_gemm_kernel<<<dim3(3, 256), 256>>>(xn, wqkvT, qkv_b, nullptr,
                                           qkvb, 384, 128, 0);
    // 3a. Scores
    score_kernel<<<BATCH * IMH, 256>>>(qkvb, scoresb);
    // 3b. Softmax + AV
    attn_av_kernel<<<NPIX, 128>>>(qkvb, scoresb, rpb, attnb);
    // 4. Proj GEMM + residual(x)
    mma_gemm_kernel<<<dim3(1, 256), 256>>>(attnb, wprojT, proj_b, x,
                                           hb, 128, 128, 1);
    // 5. LN2
    ln_kernel<<<NPIX, CDIM>>>(hb, ln2_g, ln2_b, yb);
    // 6. FC1 GEMM + GELU
    mma_gemm_kernel<<<dim3(4, 256), 256>>>(yb, wfc1T, fc1_b, nullptr,
                                           mlpb, 512, 128, 2);
    // 7. FC2 GEMM + residual(h)
    mma_gemm_kernel<<<dim3(1, 256), 256>>>(mlpb, wfc2T, fc2_b, hb,
                                           out, 128, 512, 1);
}

// round 7
// speedup vs baseline: 2.9210x; 1.7708x over previous
#include <cuda_runtime.h>
#include <cuda_bf16.h>
#include <math.h>
#include <stdint.h>

#define BATCH 4
#define IMH 64
#define IMW 64
#define CDIM 128
#define NPIX (BATCH * IMH * IMW)   // 16384
#define NHEADS 4
#define HD 32
#define NBK 7
#define HID 512

// Scratch (device globals — no allocation allowed)
__device__ __nv_bfloat16 g_xn[NPIX * CDIM];        // LN1 out (bf16, GEMM A)
__device__ float g_qkv[NPIX * 3 * CDIM];           // qkv fp32
__device__ float g_qsum[BATCH * IMH * CDIM];       // row-summed scaled q
__device__ float g_scores[BATCH * IMH * NHEADS * NBK * IMW];
__device__ __nv_bfloat16 g_attn[NPIX * CDIM];      // attn out (bf16, GEMM A)
__device__ float g_h[NPIX * CDIM];                 // residual 1 (fp32)
__device__ __nv_bfloat16 g_y[NPIX * CDIM];         // LN2 out (bf16)
__device__ __nv_bfloat16 g_mlp[NPIX * HID];        // fc1+gelu out (bf16)
// bf16 transposed weights: BT[n][k] = W[k][n]
__device__ __nv_bfloat16 g_wqkvT[384 * 128];
__device__ __nv_bfloat16 g_wprojT[128 * 128];
__device__ __nv_bfloat16 g_wfc1T[512 * 128];
__device__ __nv_bfloat16 g_wfc2T[128 * 512];

// ---------------------------------------------------------------------------
// PTX helpers (compute_103-safe)
// ---------------------------------------------------------------------------
__device__ __forceinline__ uint32_t smem_u32(const void* p) {
    uint32_t a;
    asm("{ .reg .u64 t; cvta.to.shared.u64 t, %1; cvt.u32.u64 %0, t; }"
        : "=r"(a) : "l"(p));
    return a;
}
__device__ __forceinline__ void ldm_x4(uint32_t* r, uint32_t addr) {
    asm volatile("ldmatrix.sync.aligned.m8n8.x4.shared.b16 {%0,%1,%2,%3}, [%4];"
                 : "=r"(r[0]), "=r"(r[1]), "=r"(r[2]), "=r"(r[3]) : "r"(addr));
}
__device__ __forceinline__ void ldm_x2(uint32_t* r, uint32_t addr) {
    asm volatile("ldmatrix.sync.aligned.m8n8.x2.shared.b16 {%0,%1}, [%2];"
                 : "=r"(r[0]), "=r"(r[1]) : "r"(addr));
}
__device__ __forceinline__ void mma_bf16(float* c, const uint32_t* a,
                                         const uint32_t* b) {
    asm volatile(
        "mma.sync.aligned.m16n8k16.row.col.f32.bf16.bf16.f32 "
        "{%0,%1,%2,%3}, {%4,%5,%6,%7}, {%8,%9}, {%0,%1,%2,%3};"
        : "+f"(c[0]), "+f"(c[1]), "+f"(c[2]), "+f"(c[3])
        : "r"(a[0]), "r"(a[1]), "r"(a[2]), "r"(a[3]), "r"(b[0]), "r"(b[1]));
}
__device__ __forceinline__ void cp_async16(uint32_t dst, const void* src) {
    asm volatile("cp.async.cg.shared.global [%0], [%1], 16;"
                 :: "r"(dst), "l"(src));
}
#define CP_COMMIT() asm volatile("cp.async.commit_group;")
#define CP_WAIT(n)  asm volatile("cp.async.wait_group %0;" :: "n"(n))

// ---------------------------------------------------------------------------
// Weight prep: transpose + convert to bf16
// ---------------------------------------------------------------------------
__global__ void prep_w_kernel(const float* __restrict__ qkv_w,
                              const float* __restrict__ proj_w,
                              const float* __restrict__ fc1_w,
                              const float* __restrict__ fc2_w) {
    int t = blockIdx.x * blockDim.x + threadIdx.x;
    if (t < 49152) {
        int n = t / 128, k = t % 128;
        g_wqkvT[t] = __float2bfloat16(qkv_w[k * 384 + n]);
        return;
    }
    t -= 49152;
    if (t < 16384) {
        int n = t / 128, k = t % 128;
        g_wprojT[t] = __float2bfloat16(proj_w[k * 128 + n]);
        return;
    }
    t -= 16384;
    if (t < 65536) {
        int n = t / 128, k = t % 128;
        g_wfc1T[t] = __float2bfloat16(fc1_w[k * 512 + n]);
        return;
    }
    t -= 65536;
    if (t < 65536) {
        int n = t / 512, k = t % 512;
        g_wfc2T[t] = __float2bfloat16(fc2_w[k * 128 + n]);
    }
}

// ---------------------------------------------------------------------------
// bf16 mma.sync GEMM + cp.async 2-stage pipeline.
// C[M,N] = A[M,K] @ BT[N,K]^T + bias (+res | +gelu)
// Block 64x128, BK=32, 256 threads (8 warps: 2M x 4N), warp tile 32x32.
// epi: 0=bias, 1=bias+res, 2=bias+gelu.  obf: output bf16 (else fp32).
// ---------------------------------------------------------------------------
#define BMT 64
#define BNT 128
#define BKT 32
#define ASTR 40   // 40 bf16 = 80B row stride

__global__ void mma_gemm_kernel(const __nv_bfloat16* __restrict__ A,
                                const __nv_bfloat16* __restrict__ BT,
                                const float* __restrict__ bias,
                                const float* __restrict__ res,
                                void* __restrict__ Cv,
                                int N, int Kdim, int epi, int obf) {
    __shared__ __nv_bfloat16 As[2][BMT][ASTR];
    __shared__ __nv_bfloat16 Bs[2][BNT][ASTR];

    int tid = threadIdx.x;
    int wid = tid >> 5, lane = tid & 31;
    int warp_m = wid >> 2, warp_n = wid & 3;
    int m0 = blockIdx.y * BMT;
    int n0 = blockIdx.x * BNT;

    float acc[2][4][4] = {};

    // cp.async source/dest (loop-invariant except kc)
    int ldRow = tid >> 2, ldCh = tid & 3;
    const __nv_bfloat16* Ag  = A  + (long)(m0 + ldRow) * Kdim + ldCh * 8;
    const __nv_bfloat16* Bg0 = BT + (long)(n0 + ldRow) * Kdim + ldCh * 8;
    const __nv_bfloat16* Bg1 = BT + (long)(n0 + 64 + ldRow) * Kdim + ldCh * 8;
    uint32_t aDst = smem_u32(&As[0][ldRow][ldCh * 8]);
    uint32_t bDst0 = smem_u32(&Bs[0][ldRow][ldCh * 8]);
    uint32_t bDst1 = smem_u32(&Bs[0][64 + ldRow][ldCh * 8]);
    const uint32_t A_SS = BMT * ASTR * 2;    // 5120
    const uint32_t B_SS = BNT * ASTR * 2;    // 10240

    // ldmatrix addresses (stage 0)
    uint32_t aAddr[2], bAddr[4];
    #pragma unroll
    for (int mt = 0; mt < 2; mt++)
        aAddr[mt] = smem_u32(&As[0][warp_m * 32 + mt * 16 + (lane & 15)][(lane >> 4) * 8]);
    #pragma unroll
    for (int nt = 0; nt < 4; nt++)
        bAddr[nt] = smem_u32(&Bs[0][warp_n * 32 + nt * 8 + (lane & 7)][((lane >> 3) & 1) * 8]);

    int nc = Kdim >> 5;
    // prologue
    cp_async16(aDst, Ag);
    cp_async16(bDst0, Bg0);
    cp_async16(bDst1, Bg1);
    CP_COMMIT();

    for (int c = 0; c < nc; c++) {
        if (c + 1 < nc) {
            int kc = (c + 1) << 5;
            uint32_t s = ((c + 1) & 1);
            cp_async16(aDst + s * A_SS, Ag + kc);
            cp_async16(bDst0 + s * B_SS, Bg0 + kc);
            cp_async16(bDst1 + s * B_SS, Bg1 + kc);
            CP_COMMIT();
            CP_WAIT(1);
        } else {
            CP_WAIT(0);
        }
        __syncthreads();

        uint32_t sa = (c & 1) * A_SS, sb = (c & 1) * B_SS;
        #pragma unroll
        for (int ks = 0; ks < 2; ks++) {
            uint32_t af[2][4], bf[4][2];
            #pragma unroll
            for (int mt = 0; mt < 2; mt++)
                ldm_x4(af[mt], aAddr[mt] + sa + ks * 32);
            #pragma unroll
            for (int nt = 0; nt < 4; nt++)
                ldm_x2(bf[nt], bAddr[nt] + sb + ks * 32);
            #pragma unroll
            for (int mt = 0; mt < 2; mt++)
                #pragma unroll
                for (int nt = 0; nt < 4; nt++)
                    mma_bf16(acc[mt][nt], af[mt], bf[nt]);
        }
        __syncthreads();
    }

    // Epilogue
    int trow = lane >> 2, tcol = (lane & 3) * 2;
    #pragma unroll
    for (int mt = 0; mt < 2; mt++) {
        #pragma unroll
        for (int nt = 0; nt < 4; nt++) {
            int col = n0 + warp_n * 32 + nt * 8 + tcol;
            float b0 = bias[col], b1 = bias[col + 1];
            #pragma unroll
            for (int hh = 0; hh < 2; hh++) {
                int row = m0 + warp_m * 32 + mt * 16 + trow + hh * 8;
                float v0 = acc[mt][nt][hh * 2 + 0] + b0;
                float v1 = acc[mt][nt][hh * 2 + 1] + b1;
                if (epi == 1) {
                    float2 rv = *reinterpret_cast<const float2*>(
                        &res[(long)row * N + col]);
                    v0 += rv.x; v1 += rv.y;
                } else if (epi == 2) {
                    v0 = 0.5f * v0 * (1.0f + erff(v0 * 0.7071067811865476f));
                    v1 = 0.5f * v1 * (1.0f + erff(v1 * 0.7071067811865476f));
                }
                if (obf) {
                    __nv_bfloat162 p = __float22bfloat162_rn(make_float2(v0, v1));
                    *reinterpret_cast<uint32_t*>(
                        (__nv_bfloat16*)Cv + (long)row * N + col) =
                        *reinterpret_cast<uint32_t*>(&p);
                } else {
                    float2 ov = {v0, v1};
                    *reinterpret_cast<float2*>(
                        (float*)Cv + (long)row * N + col) = ov;
                }
            }
        }
    }
}

// ---------------------------------------------------------------------------
// LayerNorm -> bf16 out
// ---------------------------------------------------------------------------
__global__ void ln_kernel(const float* __restrict__ x,
                          const float* __restrict__ gamma,
                          const float* __restrict__ beta,
                          __nv_bfloat16* __restrict__ out) {
    int row = blockIdx.x;
    int t = threadIdx.x;
    float v = x[row * CDIM + t];

    __shared__ float s1[4], s2[4];
    int lane = t & 31, warp = t >> 5;

    float ws = v;
    #pragma unroll
    for (int off = 16; off; off >>= 1) ws += __shfl_xor_sync(0xffffffffu, ws, off);
    if (lane == 0) s1[warp] = ws;
    __syncthreads();
    float mean = (s1[0] + s1[1] + s1[2] + s1[3]) * (1.0f / CDIM);

    float d = v - mean;
    float ws2 = d * d;
    #pragma unroll
    for (int off = 16; off; off >>= 1) ws2 += __shfl_xor_sync(0xffffffffu, ws2, off);
    if (lane == 0) s2[warp] = ws2;
    __syncthreads();
    float var = (s2[0] + s2[1] + s2[2] + s2[3]) * (1.0f / CDIM);

    out[row * CDIM + t] =
        __float2bfloat16(d * rsqrtf(var + 1e-5f) * gamma[t] + beta[t]);
}

// ---------------------------------------------------------------------------
// qsum: qs[by][c] = scale * sum_x q[by,x,c]   (reference contracts q over W)
// ---------------------------------------------------------------------------
__global__ void qsum_kernel(const float* __restrict__ qkv,
                            float* __restrict__ qs) {
    int by = blockIdx.x;
    int c = threadIdx.x;
    long base = (long)by * 64 * 384 + c;
    float s = 0.0f;
    #pragma unroll 8
    for (int x = 0; x < 64; x++) s += qkv[base + x * 384];
    qs[by * CDIM + c] = s * 0.17677669529663687f;
}

// ---------------------------------------------------------------------------
// sdot: one thread per (by, h, ky, nx) dot.  grid (7, 256) x 256.
// ---------------------------------------------------------------------------
__global__ void sdot_kernel(const float* __restrict__ qkv,
                            const float* __restrict__ qs,
                            float* __restrict__ scores) {
    int by = blockIdx.y;
    int d = blockIdx.x * 256 + threadIdx.x;     // 0..1791
    int h = d / 448;
    int rem = d - h * 448;
    int ky = rem >> 6, nx = rem & 63;
    int b = by >> 6, y = by & 63;
    int sy = min(max(y - 3, 0), IMH - NBK);

    const float* kb = qkv + ((long)((b * 64 + sy + ky) * 64 + nx)) * 384
                      + CDIM + h * HD;
    const float* qb = qs + by * CDIM + h * HD;
    float acc = 0.0f;
    #pragma unroll
    for (int j = 0; j < 8; j++) {
        float4 kv = *reinterpret_cast<const float4*>(kb + j * 4);
        float4 qv = *reinterpret_cast<const float4*>(qb + j * 4);
        acc += kv.x * qv.x + kv.y * qv.y + kv.z * qv.z + kv.w * qv.w;
    }
    scores[(long)by * 1792 + d] = acc;
}

// ---------------------------------------------------------------------------
// Attention AV, SMEM-tiled. Block = (by, h). 256 threads (8 warps).
// Stage V[7][64][32] as bf16x2, scores[448], rpb[169]. Phase A: softmax
// weights per pixel (warp covers 8 pixels). Phase B: pixel-pairs per warp,
// 16 lanes x 2 dims each.  Output bf16.
// ---------------------------------------------------------------------------
__global__ void attn_av_kernel(const float* __restrict__ qkv,
                               const float* __restrict__ scores,
                               const float* __restrict__ rpb,
                               __nv_bfloat16* __restrict__ out) {
    __shared__ uint32_t Vs[NBK * 64 * 16];      // bf16x2, 28672 B
    __shared__ float s_sc[NBK * 64];            // 1792 B
    __shared__ float rpb_s[169];                // 676 B
    __shared__ float wbuf[8][8][49];            // 12544 B

    int blk = blockIdx.x;
    int by = blk >> 2, h = blk & 3;
    int b = by >> 6, y = by & 63;
    int sy = min(max(y - 3, 0), IMH - NBK);
    int tid = threadIdx.x;
    int wid = tid >> 5, lane = tid & 31;

    // Stage V: 7*64*16 bf16x2 = 7168 entries
    for (int i = tid; i < NBK * 64 * 16; i += 256) {
        int ky = i >> 10;
        int rem = i & 1023;
        int col = rem >> 4, d2 = rem & 15;
        int np = (b * 64 + sy + ky) * 64 + col;
        float2 v = *reinterpret_cast<const float2*>(
            &qkv[(long)np * 384 + 2 * CDIM + h * HD + d2 * 2]);
        __nv_bfloat162 p = __float22bfloat162_rn(v);
        Vs[i] = *reinterpret_cast<uint32_t*>(&p);
    }
    for (int i = tid; i < NBK * 64; i += 256)
        s_sc[i] = scores[(long)by * 1792 + h * 448 + i];
    if (tid < 169) rpb_s[tid] = rpb[h * 169 + tid];
    __syncthreads();

    // Phase A: softmax weights for this warp's 8 pixels
    #pragma unroll 2
    for (int i = 0; i < 8; i++) {
        int x = wid * 8 + i;
        int sx = min(max(x - 3, 0), IMW - NBK);
        int ryo = (sy - y + 6) * 13 + (sx - x + 6);

        float s0, s1 = -1e30f;
        {
            int ky = lane / NBK, kx = lane - ky * NBK;
            s0 = s_sc[ky * 64 + sx + kx] + rpb_s[ryo + ky * 13 + kx];
        }
        if (lane < 17) {
            int n = lane + 32;
            int ky = n / NBK, kx = n - ky * NBK;
            s1 = s_sc[ky * 64 + sx + kx] + rpb_s[ryo + ky * 13 + kx];
        }
        float m = fmaxf(s0, s1);
        #pragma unroll
        for (int off = 16; off; off >>= 1)
            m = fmaxf(m, __shfl_xor_sync(0xffffffffu, m, off));
        float e0 = __expf(s0 - m);
        float e1 = (lane < 17) ? __expf(s1 - m) : 0.0f;
        float sum = e0 + e1;
        #pragma unroll
        for (int off = 16; off; off >>= 1)
            sum += __shfl_xor_sync(0xffffffffu, sum, off);
        float inv = 1.0f / sum;
        wbuf[wid][i][lane] = e0 * inv;
        if (lane < 17) wbuf[wid][i][lane + 32] = e1 * inv;
    }
    __syncwarp();

    // Phase B: 4 pixel-pairs per warp. lane = half*16 + d2.
    int half = lane >> 4, d2 = lane & 15;
    #pragma unroll
    for (int pi = 0; pi < 4; pi++) {
        int x = wid * 8 + pi * 2 + half;
        int sx = min(max(x - 3, 0), IMW - NBK);
        const float* wp = wbuf[wid][pi * 2 + half];

        float a0x = 0.0f, a0y = 0.0f, a1x = 0.0f, a1y = 0.0f;
        #pragma unroll
        for (int n = 0; n < 49; n++) {
            int ky = n / NBK, kx = n - ky * NBK;
            float wv = wp[n];
            uint32_t u = Vs[((ky * 64 + sx + kx) << 4) + d2];
            float lo = __uint_as_float(u << 16);
            float hi = __uint_as_float(u & 0xffff0000u);
            if (n & 1) { a1x = fmaf(wv, lo, a1x); a1y = fmaf(wv, hi, a1y); }
            else       { a0x = fmaf(wv, lo, a0x); a0y = fmaf(wv, hi, a0y); }
        }
        float vx = a0x + a1x, vy = a0y + a1y;
        int p = (b * 64 + y) * 64 + x;
        __nv_bfloat162 pk = __float22bfloat162_rn(make_float2(vx, vy));
        *reinterpret_cast<uint32_t*>(
            out + (long)p * CDIM + h * HD + d2 * 2) =
            *reinterpret_cast<uint32_t*>(&pk);
    }
}

// ---------------------------------------------------------------------------
extern "C" void kernel_launch(void* const* d_in, const int* in_sizes, int n_in,
                              void* d_out, int out_size) {
    const float* x      = (const float*)d_in[0];
    const float* ln1_g  = (const float*)d_in[1];
    const float* ln1_b  = (const float*)d_in[2];
    const float* qkv_w  = (const float*)d_in[3];
    const float* qkv_b  = (const float*)d_in[4];
    const float* rpb    = (const float*)d_in[5];
    const float* proj_w = (const float*)d_in[6];
    const float* proj_b = (const float*)d_in[7];
    const float* ln2_g  = (const float*)d_in[8];
    const float* ln2_b  = (const float*)d_in[9];
    const float* fc1_w  = (const float*)d_in[10];
    const float* fc1_b  = (const float*)d_in[11];
    const float* fc2_w  = (const float*)d_in[12];
    const float* fc2_b  = (const float*)d_in[13];
    float* out = (float*)d_out;

    __nv_bfloat16 *xn, *attnb, *yb, *mlpb;
    float *qkvb, *qsumb, *scoresb, *hb;
    cudaGetSymbolAddress((void**)&xn,      g_xn);
    cudaGetSymbolAddress((void**)&qkvb,    g_qkv);
    cudaGetSymbolAddress((void**)&qsumb,   g_qsum);
    cudaGetSymbolAddress((void**)&scoresb, g_scores);
    cudaGetSymbolAddress((void**)&attnb,   g_attn);
    cudaGetSymbolAddress((void**)&hb,      g_h);
    cudaGetSymbolAddress((void**)&yb,      g_y);
    cudaGetSymbolAddress((void**)&mlpb,    g_mlp);
    __nv_bfloat16 *wqkvT, *wprojT, *wfc1T, *wfc2T;
    cudaGetSymbolAddress((void**)&wqkvT, g_wqkvT);
    cudaGetSymbolAddress((void**)&wprojT, g_wprojT);
    cudaGetSymbolAddress((void**)&wfc1T, g_wfc1T);
    cudaGetSymbolAddress((void**)&wfc2T, g_wfc2T);

    // 0. Weight prep
    prep_w_kernel<<<768, 256>>>(qkv_w, proj_w, fc1_w, fc2_w);
    // 1. LN1 -> bf16
    ln_kernel<<<NPIX, CDIM>>>(x, ln1_g, ln1_b, xn);
    // 2. QKV GEMM (fp32 out)
    mma_gemm_kernel<<<dim3(3, 256), 256>>>(xn, wqkvT, qkv_b, nullptr,
                                           qkvb, 384, 128, 0, 0);
    // 3a. Row-summed scaled query
    qsum_kernel<<<BATCH * IMH, CDIM>>>(qkvb, qsumb);
    // 3b. Scores (one thread per dot)
    sdot_kernel<<<dim3(7, BATCH * IMH), 256>>>(qkvb, qsumb, scoresb);
    // 3c. Softmax + AV (bf16 out)
    attn_av_kernel<<<BATCH * IMH * NHEADS, 256>>>(qkvb, scoresb, rpb, attnb);
    // 4. Proj GEMM + residual(x) -> h (fp32)
    mma_gemm_kernel<<<dim3(1, 256), 256>>>(attnb, wprojT, proj_b, x,
                                           hb, 128, 128, 1, 0);
    // 5. LN2 -> bf16
    ln_kernel<<<NPIX, CDIM>>>(hb, ln2_g, ln2_b, yb);
    // 6. FC1 GEMM + GELU (bf16 out)
    mma_gemm_kernel<<<dim3(4, 256), 256>>>(yb, wfc1T, fc1_b, nullptr,
                                           mlpb, 512, 128, 2, 1);
    // 7. FC2 GEMM + residual(h) -> out (fp32)
    mma_gemm_kernel<<<dim3(1, 256), 256>>>(mlpb, wfc2T, fc2_b, hb,
                                           out, 128, 512, 1, 0);
}

// round 8
// speedup vs baseline: 3.3311x; 1.1404x over previous
#include <cuda_runtime.h>
#include <cuda_bf16.h>
#include <math.h>
#include <stdint.h>

#define BATCH 4
#define IMH 64
#define IMW 64
#define CDIM 128
#define NPIX (BATCH * IMH * IMW)   // 16384
#define NHEADS 4
#define HD 32
#define NBK 7
#define HID 512

// Scratch (device globals — no allocation allowed)
__device__ __nv_bfloat16 g_xn[NPIX * CDIM];        // LN1 out
__device__ __nv_bfloat16 g_qkv[NPIX * 3 * CDIM];   // qkv bf16
__device__ float g_scores[BATCH * IMH * NHEADS * NBK * IMW];
__device__ __nv_bfloat16 g_attn[NPIX * CDIM];      // attn out
__device__ float g_h[NPIX * CDIM];                 // residual 1 (fp32)
__device__ __nv_bfloat16 g_y[NPIX * CDIM];         // LN2 out
__device__ __nv_bfloat16 g_mlp[NPIX * HID];        // fc1+gelu out
// bf16 transposed weights: BT[n][k] = W[k][n]
__device__ __nv_bfloat16 g_wqkvT[384 * 128];
__device__ __nv_bfloat16 g_wprojT[128 * 128];
__device__ __nv_bfloat16 g_wfc1T[512 * 128];
__device__ __nv_bfloat16 g_wfc2T[128 * 512];

// ---------------------------------------------------------------------------
// PTX helpers (compute_103-safe)
// ---------------------------------------------------------------------------
__device__ __forceinline__ uint32_t smem_u32(const void* p) {
    uint32_t a;
    asm("{ .reg .u64 t; cvta.to.shared.u64 t, %1; cvt.u32.u64 %0, t; }"
        : "=r"(a) : "l"(p));
    return a;
}
__device__ __forceinline__ void ldm_x4(uint32_t* r, uint32_t addr) {
    asm volatile("ldmatrix.sync.aligned.m8n8.x4.shared.b16 {%0,%1,%2,%3}, [%4];"
                 : "=r"(r[0]), "=r"(r[1]), "=r"(r[2]), "=r"(r[3]) : "r"(addr));
}
__device__ __forceinline__ void ldm_x2(uint32_t* r, uint32_t addr) {
    asm volatile("ldmatrix.sync.aligned.m8n8.x2.shared.b16 {%0,%1}, [%2];"
                 : "=r"(r[0]), "=r"(r[1]) : "r"(addr));
}
__device__ __forceinline__ void mma_bf16(float* c, const uint32_t* a,
                                         const uint32_t* b) {
    asm volatile(
        "mma.sync.aligned.m16n8k16.row.col.f32.bf16.bf16.f32 "
        "{%0,%1,%2,%3}, {%4,%5,%6,%7}, {%8,%9}, {%0,%1,%2,%3};"
        : "+f"(c[0]), "+f"(c[1]), "+f"(c[2]), "+f"(c[3])
        : "r"(a[0]), "r"(a[1]), "r"(a[2]), "r"(a[3]), "r"(b[0]), "r"(b[1]));
}
__device__ __forceinline__ void cp_async16(uint32_t dst, const void* src) {
    asm volatile("cp.async.cg.shared.global [%0], [%1], 16;"
                 :: "r"(dst), "l"(src));
}
#define CP_COMMIT() asm volatile("cp.async.commit_group;")
#define CP_WAIT(n)  asm volatile("cp.async.wait_group %0;" :: "n"(n))

__device__ __forceinline__ float2 bf2f(uint32_t u) {
    float lo = __uint_as_float(u << 16);
    float hi = __uint_as_float(u & 0xffff0000u);
    return make_float2(lo, hi);
}

// ---------------------------------------------------------------------------
// Weight prep: transpose + convert to bf16
// ---------------------------------------------------------------------------
__global__ void prep_w_kernel(const float* __restrict__ qkv_w,
                              const float* __restrict__ proj_w,
                              const float* __restrict__ fc1_w,
                              const float* __restrict__ fc2_w) {
    int t = blockIdx.x * blockDim.x + threadIdx.x;
    if (t < 49152) {
        int n = t / 128, k = t % 128;
        g_wqkvT[t] = __float2bfloat16(qkv_w[k * 384 + n]);
        return;
    }
    t -= 49152;
    if (t < 16384) {
        int n = t / 128, k = t % 128;
        g_wprojT[t] = __float2bfloat16(proj_w[k * 128 + n]);
        return;
    }
    t -= 16384;
    if (t < 65536) {
        int n = t / 128, k = t % 128;
        g_wfc1T[t] = __float2bfloat16(fc1_w[k * 512 + n]);
        return;
    }
    t -= 65536;
    if (t < 65536) {
        int n = t / 512, k = t % 512;
        g_wfc2T[t] = __float2bfloat16(fc2_w[k * 128 + n]);
    }
}

// ---------------------------------------------------------------------------
// bf16 mma.sync GEMM + cp.async 2-stage pipeline (generic).
// Block 64x128, BK=32, 256 threads (8 warps: 2M x 4N), warp tile 32x32.
// epi: 0=bias, 1=bias+res, 2=bias+gelu.  obf: output bf16 (else fp32).
// ---------------------------------------------------------------------------
#define BMT 64
#define BNT 128
#define BKT 32
#define ASTR 40   // 40 bf16 = 80B row stride

__global__ void mma_gemm_kernel(const __nv_bfloat16* __restrict__ A,
                                const __nv_bfloat16* __restrict__ BT,
                                const float* __restrict__ bias,
                                const float* __restrict__ res,
                                void* __restrict__ Cv,
                                int N, int Kdim, int epi, int obf) {
    __shared__ __nv_bfloat16 As[2][BMT][ASTR];
    __shared__ __nv_bfloat16 Bs[2][BNT][ASTR];

    int tid = threadIdx.x;
    int wid = tid >> 5, lane = tid & 31;
    int warp_m = wid >> 2, warp_n = wid & 3;
    int m0 = blockIdx.y * BMT;
    int n0 = blockIdx.x * BNT;

    float acc[2][4][4] = {};

    int ldRow = tid >> 2, ldCh = tid & 3;
    const __nv_bfloat16* Ag  = A  + (long)(m0 + ldRow) * Kdim + ldCh * 8;
    const __nv_bfloat16* Bg0 = BT + (long)(n0 + ldRow) * Kdim + ldCh * 8;
    const __nv_bfloat16* Bg1 = BT + (long)(n0 + 64 + ldRow) * Kdim + ldCh * 8;
    uint32_t aDst = smem_u32(&As[0][ldRow][ldCh * 8]);
    uint32_t bDst0 = smem_u32(&Bs[0][ldRow][ldCh * 8]);
    uint32_t bDst1 = smem_u32(&Bs[0][64 + ldRow][ldCh * 8]);
    const uint32_t A_SS = BMT * ASTR * 2;
    const uint32_t B_SS = BNT * ASTR * 2;

    uint32_t aAddr[2], bAddr[4];
    #pragma unroll
    for (int mt = 0; mt < 2; mt++)
        aAddr[mt] = smem_u32(&As[0][warp_m * 32 + mt * 16 + (lane & 15)][(lane >> 4) * 8]);
    #pragma unroll
    for (int nt = 0; nt < 4; nt++)
        bAddr[nt] = smem_u32(&Bs[0][warp_n * 32 + nt * 8 + (lane & 7)][((lane >> 3) & 1) * 8]);

    int nc = Kdim >> 5;
    cp_async16(aDst, Ag);
    cp_async16(bDst0, Bg0);
    cp_async16(bDst1, Bg1);
    CP_COMMIT();

    for (int c = 0; c < nc; c++) {
        if (c + 1 < nc) {
            int kc = (c + 1) << 5;
            uint32_t s = ((c + 1) & 1);
            cp_async16(aDst + s * A_SS, Ag + kc);
            cp_async16(bDst0 + s * B_SS, Bg0 + kc);
            cp_async16(bDst1 + s * B_SS, Bg1 + kc);
            CP_COMMIT();
            CP_WAIT(1);
        } else {
            CP_WAIT(0);
        }
        __syncthreads();

        uint32_t sa = (c & 1) * A_SS, sb = (c & 1) * B_SS;
        #pragma unroll
        for (int ks = 0; ks < 2; ks++) {
            uint32_t af[2][4], bf[4][2];
            #pragma unroll
            for (int mt = 0; mt < 2; mt++)
                ldm_x4(af[mt], aAddr[mt] + sa + ks * 32);
            #pragma unroll
            for (int nt = 0; nt < 4; nt++)
                ldm_x2(bf[nt], bAddr[nt] + sb + ks * 32);
            #pragma unroll
            for (int mt = 0; mt < 2; mt++)
                #pragma unroll
                for (int nt = 0; nt < 4; nt++)
                    mma_bf16(acc[mt][nt], af[mt], bf[nt]);
        }
        __syncthreads();
    }

    int trow = lane >> 2, tcol = (lane & 3) * 2;
    #pragma unroll
    for (int mt = 0; mt < 2; mt++) {
        #pragma unroll
        for (int nt = 0; nt < 4; nt++) {
            int col = n0 + warp_n * 32 + nt * 8 + tcol;
            float b0 = bias[col], b1 = bias[col + 1];
            #pragma unroll
            for (int hh = 0; hh < 2; hh++) {
                int row = m0 + warp_m * 32 + mt * 16 + trow + hh * 8;
                float v0 = acc[mt][nt][hh * 2 + 0] + b0;
                float v1 = acc[mt][nt][hh * 2 + 1] + b1;
                if (epi == 1) {
                    float2 rv = *reinterpret_cast<const float2*>(
                        &res[(long)row * N + col]);
                    v0 += rv.x; v1 += rv.y;
                } else if (epi == 2) {
                    v0 = 0.5f * v0 * (1.0f + erff(v0 * 0.7071067811865476f));
                    v1 = 0.5f * v1 * (1.0f + erff(v1 * 0.7071067811865476f));
                }
                if (obf) {
                    __nv_bfloat162 p = __float22bfloat162_rn(make_float2(v0, v1));
                    *reinterpret_cast<uint32_t*>(
                        (__nv_bfloat16*)Cv + (long)row * N + col) =
                        *reinterpret_cast<uint32_t*>(&p);
                } else {
                    float2 ov = {v0, v1};
                    *reinterpret_cast<float2*>(
                        (float*)Cv + (long)row * N + col) = ov;
                }
            }
        }
    }
}

// ---------------------------------------------------------------------------
// Proj GEMM + residual + fused LN2. N=128=full row per block. Writes
// h (fp32, for FC2 residual) and y=LN2(h) (bf16).
// ---------------------------------------------------------------------------
__global__ void proj_ln_kernel(const __nv_bfloat16* __restrict__ A,
                               const __nv_bfloat16* __restrict__ BT,
                               const float* __restrict__ bias,
                               const float* __restrict__ res,
                               const float* __restrict__ g2,
                               const float* __restrict__ b2,
                               float* __restrict__ H,
                               __nv_bfloat16* __restrict__ Y) {
    const int N = 128, Kdim = 128;
    __shared__ __nv_bfloat16 As[2][BMT][ASTR];
    __shared__ __nv_bfloat16 Bs[2][BNT][ASTR];
    __shared__ float rsum[4][64], rsq[4][64];
    __shared__ float smean[64], srstd[64];

    int tid = threadIdx.x;
    int wid = tid >> 5, lane = tid & 31;
    int warp_m = wid >> 2, warp_n = wid & 3;
    int m0 = blockIdx.y * BMT;

    float acc[2][4][4] = {};

    int ldRow = tid >> 2, ldCh = tid & 3;
    const __nv_bfloat16* Ag  = A  + (long)(m0 + ldRow) * Kdim + ldCh * 8;
    const __nv_bfloat16* Bg0 = BT + (long)ldRow * Kdim + ldCh * 8;
    const __nv_bfloat16* Bg1 = BT + (long)(64 + ldRow) * Kdim + ldCh * 8;
    uint32_t aDst = smem_u32(&As[0][ldRow][ldCh * 8]);
    uint32_t bDst0 = smem_u32(&Bs[0][ldRow][ldCh * 8]);
    uint32_t bDst1 = smem_u32(&Bs[0][64 + ldRow][ldCh * 8]);
    const uint32_t A_SS = BMT * ASTR * 2;
    const uint32_t B_SS = BNT * ASTR * 2;

    uint32_t aAddr[2], bAddr[4];
    #pragma unroll
    for (int mt = 0; mt < 2; mt++)
        aAddr[mt] = smem_u32(&As[0][warp_m * 32 + mt * 16 + (lane & 15)][(lane >> 4) * 8]);
    #pragma unroll
    for (int nt = 0; nt < 4; nt++)
        bAddr[nt] = smem_u32(&Bs[0][warp_n * 32 + nt * 8 + (lane & 7)][((lane >> 3) & 1) * 8]);

    cp_async16(aDst, Ag);
    cp_async16(bDst0, Bg0);
    cp_async16(bDst1, Bg1);
    CP_COMMIT();

    for (int c = 0; c < 4; c++) {
        if (c < 3) {
            int kc = (c + 1) << 5;
            uint32_t s = ((c + 1) & 1);
            cp_async16(aDst + s * A_SS, Ag + kc);
            cp_async16(bDst0 + s * B_SS, Bg0 + kc);
            cp_async16(bDst1 + s * B_SS, Bg1 + kc);
            CP_COMMIT();
            CP_WAIT(1);
        } else {
            CP_WAIT(0);
        }
        __syncthreads();

        uint32_t sa = (c & 1) * A_SS, sb = (c & 1) * B_SS;
        #pragma unroll
        for (int ks = 0; ks < 2; ks++) {
            uint32_t af[2][4], bf[4][2];
            #pragma unroll
            for (int mt = 0; mt < 2; mt++)
                ldm_x4(af[mt], aAddr[mt] + sa + ks * 32);
            #pragma unroll
            for (int nt = 0; nt < 4; nt++)
                ldm_x2(bf[nt], bAddr[nt] + sb + ks * 32);
            #pragma unroll
            for (int mt = 0; mt < 2; mt++)
                #pragma unroll
                for (int nt = 0; nt < 4; nt++)
                    mma_bf16(acc[mt][nt], af[mt], bf[nt]);
        }
        __syncthreads();
    }

    // v = acc + bias + res, held in regs; compute row sums for LN
    int trow = lane >> 2, tcol = (lane & 3) * 2;
    float vals[2][4][2][2];
    #pragma unroll
    for (int mt = 0; mt < 2; mt++) {
        #pragma unroll
        for (int nt = 0; nt < 4; nt++) {
            int col = warp_n * 32 + nt * 8 + tcol;
            float b0 = bias[col], b1 = bias[col + 1];
            #pragma unroll
            for (int hh = 0; hh < 2; hh++) {
                int row = m0 + warp_m * 32 + mt * 16 + trow + hh * 8;
                float2 rv = *reinterpret_cast<const float2*>(&res[(long)row * N + col]);
                vals[mt][nt][hh][0] = acc[mt][nt][hh * 2 + 0] + b0 + rv.x;
                vals[mt][nt][hh][1] = acc[mt][nt][hh * 2 + 1] + b1 + rv.y;
            }
        }
    }
    // per-(mt,hh) row partials, reduce over the 4-lane col group
    #pragma unroll
    for (int mt = 0; mt < 2; mt++) {
        #pragma unroll
        for (int hh = 0; hh < 2; hh++) {
            float s = 0.0f, sq = 0.0f;
            #pragma unroll
            for (int nt = 0; nt < 4; nt++) {
                float a = vals[mt][nt][hh][0], bb = vals[mt][nt][hh][1];
                s += a + bb;
                sq += a * a + bb * bb;
            }
            s  += __shfl_xor_sync(0xffffffffu, s, 1);
            s  += __shfl_xor_sync(0xffffffffu, s, 2);
            sq += __shfl_xor_sync(0xffffffffu, sq, 1);
            sq += __shfl_xor_sync(0xffffffffu, sq, 2);
            if ((lane & 3) == 0) {
                int lr = warp_m * 32 + mt * 16 + trow + hh * 8;
                rsum[warp_n][lr] = s;
                rsq[warp_n][lr] = sq;
            }
        }
    }
    __syncthreads();
    if (tid < 64) {
        float su = rsum[0][tid] + rsum[1][tid] + rsum[2][tid] + rsum[3][tid];
        float sq = rsq[0][tid] + rsq[1][tid] + rsq[2][tid] + rsq[3][tid];
        float mean = su * (1.0f / 128.0f);
        float var = sq * (1.0f / 128.0f) - mean * mean;
        smean[tid] = mean;
        srstd[tid] = rsqrtf(var + 1e-5f);
    }
    __syncthreads();

    #pragma unroll
    for (int mt = 0; mt < 2; mt++) {
        #pragma unroll
        for (int nt = 0; nt < 4; nt++) {
            int col = warp_n * 32 + nt * 8 + tcol;
            float gg0 = g2[col], gg1 = g2[col + 1];
            float bb0 = b2[col], bb1 = b2[col + 1];
            #pragma unroll
            for (int hh = 0; hh < 2; hh++) {
                int lr = warp_m * 32 + mt * 16 + trow + hh * 8;
                int row = m0 + lr;
                float v0 = vals[mt][nt][hh][0], v1 = vals[mt][nt][hh][1];
                float2 hv = {v0, v1};
                *reinterpret_cast<float2*>(&H[(long)row * N + col]) = hv;
                float m = smean[lr], r = srstd[lr];
                float y0 = (v0 - m) * r * gg0 + bb0;
                float y1 = (v1 - m) * r * gg1 + bb1;
                __nv_bfloat162 p = __float22bfloat162_rn(make_float2(y0, y1));
                *reinterpret_cast<uint32_t*>(Y + (long)row * N + col) =
                    *reinterpret_cast<uint32_t*>(&p);
            }
        }
    }
}

// ---------------------------------------------------------------------------
// LayerNorm (LN1) -> bf16 out
// ---------------------------------------------------------------------------
__global__ void ln_kernel(const float* __restrict__ x,
                          const float* __restrict__ gamma,
                          const float* __restrict__ beta,
                          __nv_bfloat16* __restrict__ out) {
    int row = blockIdx.x;
    int t = threadIdx.x;
    float v = x[row * CDIM + t];

    __shared__ float s1[4], s2[4];
    int lane = t & 31, warp = t >> 5;

    float ws = v;
    #pragma unroll
    for (int off = 16; off; off >>= 1) ws += __shfl_xor_sync(0xffffffffu, ws, off);
    if (lane == 0) s1[warp] = ws;
    __syncthreads();
    float mean = (s1[0] + s1[1] + s1[2] + s1[3]) * (1.0f / CDIM);

    float d = v - mean;
    float ws2 = d * d;
    #pragma unroll
    for (int off = 16; off; off >>= 1) ws2 += __shfl_xor_sync(0xffffffffu, ws2, off);
    if (lane == 0) s2[warp] = ws2;
    __syncthreads();
    float var = (s2[0] + s2[1] + s2[2] + s2[3]) * (1.0f / CDIM);

    out[row * CDIM + t] =
        __float2bfloat16(d * rsqrtf(var + 1e-5f) * gamma[t] + beta[t]);
}

// ---------------------------------------------------------------------------
// Fused qsum + score dots. Block per (b,y) row; 256 threads.
// Phase 1: qs[c] = scale * sum_x q[by,x,c] (bf16 in, fp32 acc, 4-way x split)
// Phase 2: 7 dots/thread: scores[by, h, ky, nx] = qs[h*32..] . k[neighbor]
// ---------------------------------------------------------------------------
__global__ void score_fused_kernel(const __nv_bfloat16* __restrict__ qkv,
                                   float* __restrict__ scores) {
    __shared__ float part[4][CDIM];
    __shared__ float qs[CDIM];

    int by = blockIdx.x;
    int b = by >> 6, y = by & 63;
    int sy = min(max(y - 3, 0), IMH - NBK);
    int tid = threadIdx.x;

    // Phase 1: c2 = pair index (0..63), xg = x group (0..3), 16 x each
    int c2 = tid & 63, xg = tid >> 6;
    float ax = 0.0f, ay = 0.0f;
    long base = (long)(by * 64) * 384 + c2 * 2;
    #pragma unroll 4
    for (int i = 0; i < 16; i++) {
        int x = xg * 16 + i;
        uint32_t u = *reinterpret_cast<const uint32_t*>(&qkv[base + (long)x * 384]);
        float2 f = bf2f(u);
        ax += f.x; ay += f.y;
    }
    part[xg][c2 * 2] = ax;
    part[xg][c2 * 2 + 1] = ay;
    __syncthreads();
    if (tid < CDIM)
        qs[tid] = (part[0][tid] + part[1][tid] + part[2][tid] + part[3][tid])
                  * 0.17677669529663687f;
    __syncthreads();

    // Phase 2: 1792 dots, 7 per thread
    #pragma unroll
    for (int i = 0; i < 7; i++) {
        int d = i * 256 + tid;
        int h = d / 448;
        int rem = d - h * 448;
        int ky = rem >> 6, nx = rem & 63;
        const __nv_bfloat16* kb =
            qkv + ((long)((b * 64 + sy + ky) * 64 + nx)) * 384 + CDIM + h * HD;
        const float* qb = qs + h * HD;
        float acc = 0.0f;
        #pragma unroll
        for (int j = 0; j < 4; j++) {
            uint4 u = *reinterpret_cast<const uint4*>(kb + j * 8);
            float2 f0 = bf2f(u.x), f1 = bf2f(u.y), f2 = bf2f(u.z), f3 = bf2f(u.w);
            acc += f0.x * qb[j * 8 + 0] + f0.y * qb[j * 8 + 1]
                 + f1.x * qb[j * 8 + 2] + f1.y * qb[j * 8 + 3]
                 + f2.x * qb[j * 8 + 4] + f2.y * qb[j * 8 + 5]
                 + f3.x * qb[j * 8 + 6] + f3.y * qb[j * 8 + 7];
        }
        scores[(long)by * 1792 + d] = acc;
    }
}

// ---------------------------------------------------------------------------
// Attention AV, SMEM-tiled. Block = (by, h). 256 threads (8 warps).
// V already bf16 in global -> direct uint4 staging.
// ---------------------------------------------------------------------------
__global__ void attn_av_kernel(const __nv_bfloat16* __restrict__ qkv,
                               const float* __restrict__ scores,
                               const float* __restrict__ rpb,
                               __nv_bfloat16* __restrict__ out) {
    __shared__ uint32_t Vs[NBK * 64 * 16];      // bf16x2, 28672 B
    __shared__ float s_sc[NBK * 64];
    __shared__ float rpb_s[169];
    __shared__ float wbuf[8][8][49];

    int blk = blockIdx.x;
    int by = blk >> 2, h = blk & 3;
    int b = by >> 6, y = by & 63;
    int sy = min(max(y - 3, 0), IMH - NBK);
    int tid = threadIdx.x;
    int wid = tid >> 5, lane = tid & 31;

    // Stage V: 7*64*4 uint4
    for (int i = tid; i < NBK * 64 * 4; i += 256) {
        int ky = i >> 8;
        int rem = i & 255;
        int col = rem >> 2, d8 = rem & 3;
        int np = (b * 64 + sy + ky) * 64 + col;
        uint4 u = *reinterpret_cast<const uint4*>(
            &qkv[(long)np * 384 + 2 * CDIM + h * HD + d8 * 8]);
        *reinterpret_cast<uint4*>(&Vs[((ky * 64 + col) << 4) + d8 * 4]) = u;
    }
    for (int i = tid; i < NBK * 64; i += 256)
        s_sc[i] = scores[(long)by * 1792 + h * 448 + i];
    if (tid < 169) rpb_s[tid] = rpb[h * 169 + tid];
    __syncthreads();

    // Phase A: softmax weights for this warp's 8 pixels
    #pragma unroll 2
    for (int i = 0; i < 8; i++) {
        int x = wid * 8 + i;
        int sx = min(max(x - 3, 0), IMW - NBK);
        int ryo = (sy - y + 6) * 13 + (sx - x + 6);

        float s0, s1 = -1e30f;
        {
            int ky = lane / NBK, kx = lane - ky * NBK;
            s0 = s_sc[ky * 64 + sx + kx] + rpb_s[ryo + ky * 13 + kx];
        }
        if (lane < 17) {
            int n = lane + 32;
            int ky = n / NBK, kx = n - ky * NBK;
            s1 = s_sc[ky * 64 + sx + kx] + rpb_s[ryo + ky * 13 + kx];
        }
        float m = fmaxf(s0, s1);
        #pragma unroll
        for (int off = 16; off; off >>= 1)
            m = fmaxf(m, __shfl_xor_sync(0xffffffffu, m, off));
        float e0 = __expf(s0 - m);
        float e1 = (lane < 17) ? __expf(s1 - m) : 0.0f;
        float sum = e0 + e1;
        #pragma unroll
        for (int off = 16; off; off >>= 1)
            sum += __shfl_xor_sync(0xffffffffu, sum, off);
        float inv = 1.0f / sum;
        wbuf[wid][i][lane] = e0 * inv;
        if (lane < 17) wbuf[wid][i][lane + 32] = e1 * inv;
    }
    __syncwarp();

    // Phase B: 4 pixel-pairs per warp. lane = half*16 + d2.
    int half = lane >> 4, d2 = lane & 15;
    #pragma unroll
    for (int pi = 0; pi < 4; pi++) {
        int x = wid * 8 + pi * 2 + half;
        int sx = min(max(x - 3, 0), IMW - NBK);
        const float* wp = wbuf[wid][pi * 2 + half];

        float a0x = 0.0f, a0y = 0.0f, a1x = 0.0f, a1y = 0.0f;
        #pragma unroll
        for (int n = 0; n < 49; n++) {
            int ky = n / NBK, kx = n - ky * NBK;
            float wv = wp[n];
            uint32_t u = Vs[((ky * 64 + sx + kx) << 4) + d2];
            float2 f = bf2f(u);
            if (n & 1) { a1x = fmaf(wv, f.x, a1x); a1y = fmaf(wv, f.y, a1y); }
            else       { a0x = fmaf(wv, f.x, a0x); a0y = fmaf(wv, f.y, a0y); }
        }
        float vx = a0x + a1x, vy = a0y + a1y;
        int p = (b * 64 + y) * 64 + x;
        __nv_bfloat162 pk = __float22bfloat162_rn(make_float2(vx, vy));
        *reinterpret_cast<uint32_t*>(
            out + (long)p * CDIM + h * HD + d2 * 2) =
            *reinterpret_cast<uint32_t*>(&pk);
    }
}

// ---------------------------------------------------------------------------
extern "C" void kernel_launch(void* const* d_in, const int* in_sizes, int n_in,
                              void* d_out, int out_size) {
    const float* x      = (const float*)d_in[0];
    const float* ln1_g  = (const float*)d_in[1];
    const float* ln1_b  = (const float*)d_in[2];
    const float* qkv_w  = (const float*)d_in[3];
    const float* qkv_b  = (const float*)d_in[4];
    const float* rpb    = (const float*)d_in[5];
    const float* proj_w = (const float*)d_in[6];
    const float* proj_b = (const float*)d_in[7];
    const float* ln2_g  = (const float*)d_in[8];
    const float* ln2_b  = (const float*)d_in[9];
    const float* fc1_w  = (const float*)d_in[10];
    const float* fc1_b  = (const float*)d_in[11];
    const float* fc2_w  = (const float*)d_in[12];
    const float* fc2_b  = (const float*)d_in[13];
    float* out = (float*)d_out;

    __nv_bfloat16 *xn, *qkvb, *attnb, *yb, *mlpb;
    float *scoresb, *hb;
    cudaGetSymbolAddress((void**)&xn,      g_xn);
    cudaGetSymbolAddress((void**)&qkvb,    g_qkv);
    cudaGetSymbolAddress((void**)&scoresb, g_scores);
    cudaGetSymbolAddress((void**)&attnb,   g_attn);
    cudaGetSymbolAddress((void**)&hb,      g_h);
    cudaGetSymbolAddress((void**)&yb,      g_y);
    cudaGetSymbolAddress((void**)&mlpb,    g_mlp);
    __nv_bfloat16 *wqkvT, *wprojT, *wfc1T, *wfc2T;
    cudaGetSymbolAddress((void**)&wqkvT, g_wqkvT);
    cudaGetSymbolAddress((void**)&wprojT, g_wprojT);
    cudaGetSymbolAddress((void**)&wfc1T, g_wfc1T);
    cudaGetSymbolAddress((void**)&wfc2T, g_wfc2T);

    // 0. Weight prep
    prep_w_kernel<<<768, 256>>>(qkv_w, proj_w, fc1_w, fc2_w);
    // 1. LN1 -> bf16
    ln_kernel<<<NPIX, CDIM>>>(x, ln1_g, ln1_b, xn);
    // 2. QKV GEMM -> bf16 qkv
    mma_gemm_kernel<<<dim3(3, 256), 256>>>(xn, wqkvT, qkv_b, nullptr,
                                           qkvb, 384, 128, 0, 1);
    // 3a. Fused qsum + scores
    score_fused_kernel<<<BATCH * IMH, 256>>>(qkvb, scoresb);
    // 3b. Softmax + AV (bf16 out)
    attn_av_kernel<<<BATCH * IMH * NHEADS, 256>>>(qkvb, scoresb, rpb, attnb);
    // 4. Proj GEMM + residual(x) + LN2 -> h (fp32) & y (bf16)
    proj_ln_kernel<<<dim3(1, 256), 256>>>(attnb, wprojT, proj_b, x,
                                          ln2_g, ln2_b, hb, yb);
    // 5. FC1 GEMM + GELU (bf16 out)
    mma_gemm_kernel<<<dim3(4, 256), 256>>>(yb, wfc1T, fc1_b, nullptr,
                                           mlpb, 512, 128, 2, 1);
    // 6. FC2 GEMM + residual(h) -> out (fp32)
    mma_gemm_kernel<<<dim3(1, 256), 256>>>(mlpb, wfc2T, fc2_b, hb,
                                           out, 128, 512, 1, 0);
}

// round 9
// speedup vs baseline: 3.4267x; 1.0287x over previous
#include <cuda_runtime.h>
#include <cuda_bf16.h>
#include <math.h>
#include <stdint.h>

#define BATCH 4
#define IMH 64
#define IMW 64
#define CDIM 128
#define NPIX (BATCH * IMH * IMW)   // 16384
#define NHEADS 4
#define HD 32
#define NBK 7
#define HID 512

// Scratch (device globals — no allocation allowed)
__device__ __nv_bfloat16 g_xn[NPIX * CDIM];        // LN1 out
__device__ __nv_bfloat16 g_qkv[NPIX * 3 * CDIM];   // qkv bf16
__device__ __nv_bfloat16 g_attn[NPIX * CDIM];      // attn out
__device__ float g_h[NPIX * CDIM];                 // residual 1 (fp32)
__device__ __nv_bfloat16 g_y[NPIX * CDIM];         // LN2 out
__device__ __nv_bfloat16 g_mlp[NPIX * HID];        // fc1+gelu out
// bf16 transposed weights: BT[n][k] = W[k][n]
__device__ __nv_bfloat16 g_wqkvT[384 * 128];
__device__ __nv_bfloat16 g_wprojT[128 * 128];
__device__ __nv_bfloat16 g_wfc1T[512 * 128];
__device__ __nv_bfloat16 g_wfc2T[128 * 512];

// ---------------------------------------------------------------------------
// PTX helpers (compute_103-safe)
// ---------------------------------------------------------------------------
__device__ __forceinline__ uint32_t smem_u32(const void* p) {
    uint32_t a;
    asm("{ .reg .u64 t; cvta.to.shared.u64 t, %1; cvt.u32.u64 %0, t; }"
        : "=r"(a) : "l"(p));
    return a;
}
__device__ __forceinline__ void ldm_x4(uint32_t* r, uint32_t addr) {
    asm volatile("ldmatrix.sync.aligned.m8n8.x4.shared.b16 {%0,%1,%2,%3}, [%4];"
                 : "=r"(r[0]), "=r"(r[1]), "=r"(r[2]), "=r"(r[3]) : "r"(addr));
}
__device__ __forceinline__ void ldm_x2(uint32_t* r, uint32_t addr) {
    asm volatile("ldmatrix.sync.aligned.m8n8.x2.shared.b16 {%0,%1}, [%2];"
                 : "=r"(r[0]), "=r"(r[1]) : "r"(addr));
}
__device__ __forceinline__ void mma_bf16(float* c, const uint32_t* a,
                                         const uint32_t* b) {
    asm volatile(
        "mma.sync.aligned.m16n8k16.row.col.f32.bf16.bf16.f32 "
        "{%0,%1,%2,%3}, {%4,%5,%6,%7}, {%8,%9}, {%0,%1,%2,%3};"
        : "+f"(c[0]), "+f"(c[1]), "+f"(c[2]), "+f"(c[3])
        : "r"(a[0]), "r"(a[1]), "r"(a[2]), "r"(a[3]), "r"(b[0]), "r"(b[1]));
}
__device__ __forceinline__ void cp_async16(uint32_t dst, const void* src) {
    asm volatile("cp.async.cg.shared.global [%0], [%1], 16;"
                 :: "r"(dst), "l"(src));
}
#define CP_COMMIT() asm volatile("cp.async.commit_group;")
#define CP_WAIT(n)  asm volatile("cp.async.wait_group %0;" :: "n"(n))

__device__ __forceinline__ float2 bf2f(uint32_t u) {
    float lo = __uint_as_float(u << 16);
    float hi = __uint_as_float(u & 0xffff0000u);
    return make_float2(lo, hi);
}

// ---------------------------------------------------------------------------
// Weight prep: transpose + convert to bf16
// ---------------------------------------------------------------------------
__global__ void prep_w_kernel(const float* __restrict__ qkv_w,
                              const float* __restrict__ proj_w,
                              const float* __restrict__ fc1_w,
                              const float* __restrict__ fc2_w) {
    int t = blockIdx.x * blockDim.x + threadIdx.x;
    if (t < 49152) {
        int n = t / 128, k = t % 128;
        g_wqkvT[t] = __float2bfloat16(qkv_w[k * 384 + n]);
        return;
    }
    t -= 49152;
    if (t < 16384) {
        int n = t / 128, k = t % 128;
        g_wprojT[t] = __float2bfloat16(proj_w[k * 128 + n]);
        return;
    }
    t -= 16384;
    if (t < 65536) {
        int n = t / 128, k = t % 128;
        g_wfc1T[t] = __float2bfloat16(fc1_w[k * 512 + n]);
        return;
    }
    t -= 65536;
    if (t < 65536) {
        int n = t / 512, k = t % 512;
        g_wfc2T[t] = __float2bfloat16(fc2_w[k * 128 + n]);
    }
}

// ---------------------------------------------------------------------------
// bf16 mma.sync GEMM + cp.async 2-stage pipeline (generic).
// Block 64x128, BK=32, 256 threads (8 warps: 2M x 4N), warp tile 32x32.
// epi: 0=bias, 1=bias+res, 2=bias+gelu.  obf: output bf16 (else fp32).
// ---------------------------------------------------------------------------
#define BMT 64
#define BNT 128
#define BKT 32
#define ASTR 40   // 40 bf16 = 80B row stride

__global__ void mma_gemm_kernel(const __nv_bfloat16* __restrict__ A,
                                const __nv_bfloat16* __restrict__ BT,
                                const float* __restrict__ bias,
                                const float* __restrict__ res,
                                void* __restrict__ Cv,
                                int N, int Kdim, int epi, int obf) {
    __shared__ __nv_bfloat16 As[2][BMT][ASTR];
    __shared__ __nv_bfloat16 Bs[2][BNT][ASTR];

    int tid = threadIdx.x;
    int wid = tid >> 5, lane = tid & 31;
    int warp_m = wid >> 2, warp_n = wid & 3;
    int m0 = blockIdx.y * BMT;
    int n0 = blockIdx.x * BNT;

    float acc[2][4][4] = {};

    int ldRow = tid >> 2, ldCh = tid & 3;
    const __nv_bfloat16* Ag  = A  + (long)(m0 + ldRow) * Kdim + ldCh * 8;
    const __nv_bfloat16* Bg0 = BT + (long)(n0 + ldRow) * Kdim + ldCh * 8;
    const __nv_bfloat16* Bg1 = BT + (long)(n0 + 64 + ldRow) * Kdim + ldCh * 8;
    uint32_t aDst = smem_u32(&As[0][ldRow][ldCh * 8]);
    uint32_t bDst0 = smem_u32(&Bs[0][ldRow][ldCh * 8]);
    uint32_t bDst1 = smem_u32(&Bs[0][64 + ldRow][ldCh * 8]);
    const uint32_t A_SS = BMT * ASTR * 2;
    const uint32_t B_SS = BNT * ASTR * 2;

    uint32_t aAddr[2], bAddr[4];
    #pragma unroll
    for (int mt = 0; mt < 2; mt++)
        aAddr[mt] = smem_u32(&As[0][warp_m * 32 + mt * 16 + (lane & 15)][(lane >> 4) * 8]);
    #pragma unroll
    for (int nt = 0; nt < 4; nt++)
        bAddr[nt] = smem_u32(&Bs[0][warp_n * 32 + nt * 8 + (lane & 7)][((lane >> 3) & 1) * 8]);

    int nc = Kdim >> 5;
    cp_async16(aDst, Ag);
    cp_async16(bDst0, Bg0);
    cp_async16(bDst1, Bg1);
    CP_COMMIT();

    for (int c = 0; c < nc; c++) {
        if (c + 1 < nc) {
            int kc = (c + 1) << 5;
            uint32_t s = ((c + 1) & 1);
            cp_async16(aDst + s * A_SS, Ag + kc);
            cp_async16(bDst0 + s * B_SS, Bg0 + kc);
            cp_async16(bDst1 + s * B_SS, Bg1 + kc);
            CP_COMMIT();
            CP_WAIT(1);
        } else {
            CP_WAIT(0);
        }
        __syncthreads();

        uint32_t sa = (c & 1) * A_SS, sb = (c & 1) * B_SS;
        #pragma unroll
        for (int ks = 0; ks < 2; ks++) {
            uint32_t af[2][4], bf[4][2];
            #pragma unroll
            for (int mt = 0; mt < 2; mt++)
                ldm_x4(af[mt], aAddr[mt] + sa + ks * 32);
            #pragma unroll
            for (int nt = 0; nt < 4; nt++)
                ldm_x2(bf[nt], bAddr[nt] + sb + ks * 32);
            #pragma unroll
            for (int mt = 0; mt < 2; mt++)
                #pragma unroll
                for (int nt = 0; nt < 4; nt++)
                    mma_bf16(acc[mt][nt], af[mt], bf[nt]);
        }
        __syncthreads();
    }

    int trow = lane >> 2, tcol = (lane & 3) * 2;
    #pragma unroll
    for (int mt = 0; mt < 2; mt++) {
        #pragma unroll
        for (int nt = 0; nt < 4; nt++) {
            int col = n0 + warp_n * 32 + nt * 8 + tcol;
            float b0 = bias[col], b1 = bias[col + 1];
            #pragma unroll
            for (int hh = 0; hh < 2; hh++) {
                int row = m0 + warp_m * 32 + mt * 16 + trow + hh * 8;
                float v0 = acc[mt][nt][hh * 2 + 0] + b0;
                float v1 = acc[mt][nt][hh * 2 + 1] + b1;
                if (epi == 1) {
                    float2 rv = *reinterpret_cast<const float2*>(
                        &res[(long)row * N + col]);
                    v0 += rv.x; v1 += rv.y;
                } else if (epi == 2) {
                    v0 = 0.5f * v0 * (1.0f + erff(v0 * 0.7071067811865476f));
                    v1 = 0.5f * v1 * (1.0f + erff(v1 * 0.7071067811865476f));
                }
                if (obf) {
                    __nv_bfloat162 p = __float22bfloat162_rn(make_float2(v0, v1));
                    *reinterpret_cast<uint32_t*>(
                        (__nv_bfloat16*)Cv + (long)row * N + col) =
                        *reinterpret_cast<uint32_t*>(&p);
                } else {
                    float2 ov = {v0, v1};
                    *reinterpret_cast<float2*>(
                        (float*)Cv + (long)row * N + col) = ov;
                }
            }
        }
    }
}

// ---------------------------------------------------------------------------
// Proj GEMM + residual + fused LN2. N=128=full row per block. Writes
// h (fp32, for FC2 residual) and y=LN2(h) (bf16).
// ---------------------------------------------------------------------------
__global__ void proj_ln_kernel(const __nv_bfloat16* __restrict__ A,
                               const __nv_bfloat16* __restrict__ BT,
                               const float* __restrict__ bias,
                               const float* __restrict__ res,
                               const float* __restrict__ g2,
                               const float* __restrict__ b2,
                               float* __restrict__ H,
                               __nv_bfloat16* __restrict__ Y) {
    const int N = 128, Kdim = 128;
    __shared__ __nv_bfloat16 As[2][BMT][ASTR];
    __shared__ __nv_bfloat16 Bs[2][BNT][ASTR];
    __shared__ float rsum[4][64], rsq[4][64];
    __shared__ float smean[64], srstd[64];

    int tid = threadIdx.x;
    int wid = tid >> 5, lane = tid & 31;
    int warp_m = wid >> 2, warp_n = wid & 3;
    int m0 = blockIdx.y * BMT;

    float acc[2][4][4] = {};

    int ldRow = tid >> 2, ldCh = tid & 3;
    const __nv_bfloat16* Ag  = A  + (long)(m0 + ldRow) * Kdim + ldCh * 8;
    const __nv_bfloat16* Bg0 = BT + (long)ldRow * Kdim + ldCh * 8;
    const __nv_bfloat16* Bg1 = BT + (long)(64 + ldRow) * Kdim + ldCh * 8;
    uint32_t aDst = smem_u32(&As[0][ldRow][ldCh * 8]);
    uint32_t bDst0 = smem_u32(&Bs[0][ldRow][ldCh * 8]);
    uint32_t bDst1 = smem_u32(&Bs[0][64 + ldRow][ldCh * 8]);
    const uint32_t A_SS = BMT * ASTR * 2;
    const uint32_t B_SS = BNT * ASTR * 2;

    uint32_t aAddr[2], bAddr[4];
    #pragma unroll
    for (int mt = 0; mt < 2; mt++)
        aAddr[mt] = smem_u32(&As[0][warp_m * 32 + mt * 16 + (lane & 15)][(lane >> 4) * 8]);
    #pragma unroll
    for (int nt = 0; nt < 4; nt++)
        bAddr[nt] = smem_u32(&Bs[0][warp_n * 32 + nt * 8 + (lane & 7)][((lane >> 3) & 1) * 8]);

    cp_async16(aDst, Ag);
    cp_async16(bDst0, Bg0);
    cp_async16(bDst1, Bg1);
    CP_COMMIT();

    for (int c = 0; c < 4; c++) {
        if (c < 3) {
            int kc = (c + 1) << 5;
            uint32_t s = ((c + 1) & 1);
            cp_async16(aDst + s * A_SS, Ag + kc);
            cp_async16(bDst0 + s * B_SS, Bg0 + kc);
            cp_async16(bDst1 + s * B_SS, Bg1 + kc);
            CP_COMMIT();
            CP_WAIT(1);
        } else {
            CP_WAIT(0);
        }
        __syncthreads();

        uint32_t sa = (c & 1) * A_SS, sb = (c & 1) * B_SS;
        #pragma unroll
        for (int ks = 0; ks < 2; ks++) {
            uint32_t af[2][4], bf[4][2];
            #pragma unroll
            for (int mt = 0; mt < 2; mt++)
                ldm_x4(af[mt], aAddr[mt] + sa + ks * 32);
            #pragma unroll
            for (int nt = 0; nt < 4; nt++)
                ldm_x2(bf[nt], bAddr[nt] + sb + ks * 32);
            #pragma unroll
            for (int mt = 0; mt < 2; mt++)
                #pragma unroll
                for (int nt = 0; nt < 4; nt++)
                    mma_bf16(acc[mt][nt], af[mt], bf[nt]);
        }
        __syncthreads();
    }

    int trow = lane >> 2, tcol = (lane & 3) * 2;
    float vals[2][4][2][2];
    #pragma unroll
    for (int mt = 0; mt < 2; mt++) {
        #pragma unroll
        for (int nt = 0; nt < 4; nt++) {
            int col = warp_n * 32 + nt * 8 + tcol;
            float b0 = bias[col], b1 = bias[col + 1];
            #pragma unroll
            for (int hh = 0; hh < 2; hh++) {
                int row = m0 + warp_m * 32 + mt * 16 + trow + hh * 8;
                float2 rv = *reinterpret_cast<const float2*>(&res[(long)row * N + col]);
                vals[mt][nt][hh][0] = acc[mt][nt][hh * 2 + 0] + b0 + rv.x;
                vals[mt][nt][hh][1] = acc[mt][nt][hh * 2 + 1] + b1 + rv.y;
            }
        }
    }
    #pragma unroll
    for (int mt = 0; mt < 2; mt++) {
        #pragma unroll
        for (int hh = 0; hh < 2; hh++) {
            float s = 0.0f, sq = 0.0f;
            #pragma unroll
            for (int nt = 0; nt < 4; nt++) {
                float a = vals[mt][nt][hh][0], bb = vals[mt][nt][hh][1];
                s += a + bb;
                sq += a * a + bb * bb;
            }
            s  += __shfl_xor_sync(0xffffffffu, s, 1);
            s  += __shfl_xor_sync(0xffffffffu, s, 2);
            sq += __shfl_xor_sync(0xffffffffu, sq, 1);
            sq += __shfl_xor_sync(0xffffffffu, sq, 2);
            if ((lane & 3) == 0) {
                int lr = warp_m * 32 + mt * 16 + trow + hh * 8;
                rsum[warp_n][lr] = s;
                rsq[warp_n][lr] = sq;
            }
        }
    }
    __syncthreads();
    if (tid < 64) {
        float su = rsum[0][tid] + rsum[1][tid] + rsum[2][tid] + rsum[3][tid];
        float sq = rsq[0][tid] + rsq[1][tid] + rsq[2][tid] + rsq[3][tid];
        float mean = su * (1.0f / 128.0f);
        float var = sq * (1.0f / 128.0f) - mean * mean;
        smean[tid] = mean;
        srstd[tid] = rsqrtf(var + 1e-5f);
    }
    __syncthreads();

    #pragma unroll
    for (int mt = 0; mt < 2; mt++) {
        #pragma unroll
        for (int nt = 0; nt < 4; nt++) {
            int col = warp_n * 32 + nt * 8 + tcol;
            float gg0 = g2[col], gg1 = g2[col + 1];
            float bb0 = b2[col], bb1 = b2[col + 1];
            #pragma unroll
            for (int hh = 0; hh < 2; hh++) {
                int lr = warp_m * 32 + mt * 16 + trow + hh * 8;
                int row = m0 + lr;
                float v0 = vals[mt][nt][hh][0], v1 = vals[mt][nt][hh][1];
                float2 hv = {v0, v1};
                *reinterpret_cast<float2*>(&H[(long)row * N + col]) = hv;
                float m = smean[lr], r = srstd[lr];
                float y0 = (v0 - m) * r * gg0 + bb0;
                float y1 = (v1 - m) * r * gg1 + bb1;
                __nv_bfloat162 p = __float22bfloat162_rn(make_float2(y0, y1));
                *reinterpret_cast<uint32_t*>(Y + (long)row * N + col) =
                    *reinterpret_cast<uint32_t*>(&p);
            }
        }
    }
}

// ---------------------------------------------------------------------------
// LayerNorm (LN1) -> bf16 out
// ---------------------------------------------------------------------------
__global__ void ln_kernel(const float* __restrict__ x,
                          const float* __restrict__ gamma,
                          const float* __restrict__ beta,
                          __nv_bfloat16* __restrict__ out) {
    int row = blockIdx.x;
    int t = threadIdx.x;
    float v = x[row * CDIM + t];

    __shared__ float s1[4], s2[4];
    int lane = t & 31, warp = t >> 5;

    float ws = v;
    #pragma unroll
    for (int off = 16; off; off >>= 1) ws += __shfl_xor_sync(0xffffffffu, ws, off);
    if (lane == 0) s1[warp] = ws;
    __syncthreads();
    float mean = (s1[0] + s1[1] + s1[2] + s1[3]) * (1.0f / CDIM);

    float d = v - mean;
    float ws2 = d * d;
    #pragma unroll
    for (int off = 16; off; off >>= 1) ws2 += __shfl_xor_sync(0xffffffffu, ws2, off);
    if (lane == 0) s2[warp] = ws2;
    __syncthreads();
    float var = (s2[0] + s2[1] + s2[2] + s2[3]) * (1.0f / CDIM);

    out[row * CDIM + t] =
        __float2bfloat16(d * rsqrtf(var + 1e-5f) * gamma[t] + beta[t]);
}

// ---------------------------------------------------------------------------
// Fully fused neighborhood attention. Block = (by, h). 256 threads (8 warps).
// 1. qsum_h[32] = scale * sum_x q[by,x,h*32+..]  (warp shfl + SMEM reduce)
// 2. 448 score dots (qs . K[neighbor]) into SMEM
// 3. per-pixel softmax weights (Phase A), AV accumulate (Phase B)
// ---------------------------------------------------------------------------
__global__ void natt_kernel(const __nv_bfloat16* __restrict__ qkv,
                            const float* __restrict__ rpb,
                            __nv_bfloat16* __restrict__ out) {
    __shared__ uint32_t Vs[NBK * 64 * 16];      // 28672 B
    __shared__ float s_sc[NBK * 64];            // 1792 B
    __shared__ float rpb_s[169];                // 676 B
    __shared__ float wbuf[8][8][49];            // 12544 B
    __shared__ float qpart[8][HD];              // 1024 B
    __shared__ float qs[HD];                    // 128 B

    int blk = blockIdx.x;
    int by = blk >> 2, h = blk & 3;
    int b = by >> 6, y = by & 63;
    int sy = min(max(y - 3, 0), IMH - NBK);
    int tid = threadIdx.x;
    int wid = tid >> 5, lane = tid & 31;

    // --- qsum partial: thread = (x = tid>>2, dg = tid&3), 8 channels each
    {
        int x = tid >> 2, dg = tid & 3;
        uint4 u = *reinterpret_cast<const uint4*>(
            &qkv[((long)(by * 64 + x)) * 384 + h * HD + dg * 8]);
        float2 f0 = bf2f(u.x), f1 = bf2f(u.y), f2 = bf2f(u.z), f3 = bf2f(u.w);
        float v[8] = {f0.x, f0.y, f1.x, f1.y, f2.x, f2.y, f3.x, f3.y};
        // reduce over the 8 x's in this warp (lanes with same dg: stride 4)
        #pragma unroll
        for (int i = 0; i < 8; i++) {
            v[i] += __shfl_xor_sync(0xffffffffu, v[i], 4);
            v[i] += __shfl_xor_sync(0xffffffffu, v[i], 8);
            v[i] += __shfl_xor_sync(0xffffffffu, v[i], 16);
        }
        if (lane < 4) {
            #pragma unroll
            for (int i = 0; i < 8; i++)
                qpart[wid][lane * 8 + i] = v[i];
        }
    }

    // --- Stage V: 7*64*4 uint4 (overlaps with qsum finishing)
    for (int i = tid; i < NBK * 64 * 4; i += 256) {
        int ky = i >> 8;
        int rem = i & 255;
        int col = rem >> 2, d8 = rem & 3;
        int np = (b * 64 + sy + ky) * 64 + col;
        uint4 u = *reinterpret_cast<const uint4*>(
            &qkv[(long)np * 384 + 2 * CDIM + h * HD + d8 * 8]);
        *reinterpret_cast<uint4*>(&Vs[((ky * 64 + col) << 4) + d8 * 4]) = u;
    }
    if (tid < 169) rpb_s[tid] = rpb[h * 169 + tid];
    __syncthreads();

    if (tid < HD) {
        float s = 0.0f;
        #pragma unroll
        for (int w = 0; w < 8; w++) s += qpart[w][tid];
        qs[tid] = s * 0.17677669529663687f;
    }
    __syncthreads();

    // --- Score dots: 448 dots, <=2 per thread
    #pragma unroll
    for (int rep = 0; rep < 2; rep++) {
        int d = rep * 256 + tid;
        if (d < NBK * 64) {
            int ky = d >> 6, nx = d & 63;
            const __nv_bfloat16* kb =
                qkv + ((long)((b * 64 + sy + ky) * 64 + nx)) * 384 + CDIM + h * HD;
            float acc = 0.0f;
            #pragma unroll
            for (int j = 0; j < 4; j++) {
                uint4 u = *reinterpret_cast<const uint4*>(kb + j * 8);
                float2 f0 = bf2f(u.x), f1 = bf2f(u.y), f2 = bf2f(u.z), f3 = bf2f(u.w);
                acc += f0.x * qs[j * 8 + 0] + f0.y * qs[j * 8 + 1]
                     + f1.x * qs[j * 8 + 2] + f1.y * qs[j * 8 + 3]
                     + f2.x * qs[j * 8 + 4] + f2.y * qs[j * 8 + 5]
                     + f3.x * qs[j * 8 + 6] + f3.y * qs[j * 8 + 7];
            }
            s_sc[d] = acc;
        }
    }
    __syncthreads();

    // --- Phase A: softmax weights for this warp's 8 pixels
    #pragma unroll 2
    for (int i = 0; i < 8; i++) {
        int x = wid * 8 + i;
        int sx = min(max(x - 3, 0), IMW - NBK);
        int ryo = (sy - y + 6) * 13 + (sx - x + 6);

        float s0, s1 = -1e30f;
        {
            int ky = lane / NBK, kx = lane - ky * NBK;
            s0 = s_sc[ky * 64 + sx + kx] + rpb_s[ryo + ky * 13 + kx];
        }
        if (lane < 17) {
            int n = lane + 32;
            int ky = n / NBK, kx = n - ky * NBK;
            s1 = s_sc[ky * 64 + sx + kx] + rpb_s[ryo + ky * 13 + kx];
        }
        float m = fmaxf(s0, s1);
        #pragma unroll
        for (int off = 16; off; off >>= 1)
            m = fmaxf(m, __shfl_xor_sync(0xffffffffu, m, off));
        float e0 = __expf(s0 - m);
        float e1 = (lane < 17) ? __expf(s1 - m) : 0.0f;
        float sum = e0 + e1;
        #pragma unroll
        for (int off = 16; off; off >>= 1)
            sum += __shfl_xor_sync(0xffffffffu, sum, off);
        float inv = 1.0f / sum;
        wbuf[wid][i][lane] = e0 * inv;
        if (lane < 17) wbuf[wid][i][lane + 32] = e1 * inv;
    }
    __syncwarp();

    // --- Phase B: 4 pixel-pairs per warp. lane = half*16 + d2.
    int half = lane >> 4, d2 = lane & 15;
    #pragma unroll
    for (int pi = 0; pi < 4; pi++) {
        int x = wid * 8 + pi * 2 + half;
        int sx = min(max(x - 3, 0), IMW - NBK);
        const float* wp = wbuf[wid][pi * 2 + half];

        float a0x = 0.0f, a0y = 0.0f, a1x = 0.0f, a1y = 0.0f;
        #pragma unroll
        for (int n = 0; n < 49; n++) {
            int ky = n / NBK, kx = n - ky * NBK;
            float wv = wp[n];
            uint32_t u = Vs[((ky * 64 + sx + kx) << 4) + d2];
            float2 f = bf2f(u);
            if (n & 1) { a1x = fmaf(wv, f.x, a1x); a1y = fmaf(wv, f.y, a1y); }
            else       { a0x = fmaf(wv, f.x, a0x); a0y = fmaf(wv, f.y, a0y); }
        }
        float vx = a0x + a1x, vy = a0y + a1y;
        int p = (b * 64 + y) * 64 + x;
        __nv_bfloat162 pk = __float22bfloat162_rn(make_float2(vx, vy));
        *reinterpret_cast<uint32_t*>(
            out + (long)p * CDIM + h * HD + d2 * 2) =
            *reinterpret_cast<uint32_t*>(&pk);
    }
}

// ---------------------------------------------------------------------------
extern "C" void kernel_launch(void* const* d_in, const int* in_sizes, int n_in,
                              void* d_out, int out_size) {
    const float* x      = (const float*)d_in[0];
    const float* ln1_g  = (const float*)d_in[1];
    const float* ln1_b  = (const float*)d_in[2];
    const float* qkv_w  = (const float*)d_in[3];
    const float* qkv_b  = (const float*)d_in[4];
    const float* rpb    = (const float*)d_in[5];
    const float* proj_w = (const float*)d_in[6];
    const float* proj_b = (const float*)d_in[7];
    const float* ln2_g  = (const float*)d_in[8];
    const float* ln2_b  = (const float*)d_in[9];
    const float* fc1_w  = (const float*)d_in[10];
    const float* fc1_b  = (const float*)d_in[11];
    const float* fc2_w  = (const float*)d_in[12];
    const float* fc2_b  = (const float*)d_in[13];
    float* out = (float*)d_out;

    __nv_bfloat16 *xn, *qkvb, *attnb, *yb, *mlpb;
    float *hb;
    cudaGetSymbolAddress((void**)&xn,      g_xn);
    cudaGetSymbolAddress((void**)&qkvb,    g_qkv);
    cudaGetSymbolAddress((void**)&attnb,   g_attn);
    cudaGetSymbolAddress((void**)&hb,      g_h);
    cudaGetSymbolAddress((void**)&yb,      g_y);
    cudaGetSymbolAddress((void**)&mlpb,    g_mlp);
    __nv_bfloat16 *wqkvT, *wprojT, *wfc1T, *wfc2T;
    cudaGetSymbolAddress((void**)&wqkvT, g_wqkvT);
    cudaGetSymbolAddress((void**)&wprojT, g_wprojT);
    cudaGetSymbolAddress((void**)&wfc1T, g_wfc1T);
    cudaGetSymbolAddress((void**)&wfc2T, g_wfc2T);

    // 0. Weight prep
    prep_w_kernel<<<768, 256>>>(qkv_w, proj_w, fc1_w, fc2_w);
    // 1. LN1 -> bf16
    ln_kernel<<<NPIX, CDIM>>>(x, ln1_g, ln1_b, xn);
    // 2. QKV GEMM -> bf16 qkv
    mma_gemm_kernel<<<dim3(3, 256), 256>>>(xn, wqkvT, qkv_b, nullptr,
                                           qkvb, 384, 128, 0, 1);
    // 3. Fused neighborhood attention (qsum + scores + softmax + AV)
    natt_kernel<<<BATCH * IMH * NHEADS, 256>>>(qkvb, rpb, attnb);
    // 4. Proj GEMM + residual(x) + LN2 -> h (fp32) & y (bf16)
    proj_ln_kernel<<<dim3(1, 256), 256>>>(attnb, wprojT, proj_b, x,
                                          ln2_g, ln2_b, hb, yb);
    // 5. FC1 GEMM + GELU (bf16 out)
    mma_gemm_kernel<<<dim3(4, 256), 256>>>(yb, wfc1T, fc1_b, nullptr,
                                           mlpb, 512, 128, 2, 1);
    // 6. FC2 GEMM + residual(h) -> out (fp32)
    mma_gemm_kernel<<<dim3(1, 256), 256>>>(mlpb, wfc2T, fc2_b, hb,
                                           out, 128, 512, 1, 0);
}

// round 11
// speedup vs baseline: 3.5765x; 1.0437x over previous
#include <cuda_runtime.h>
#include <cuda_bf16.h>
#include <math.h>
#include <stdint.h>

#define BATCH 4
#define IMH 64
#define IMW 64
#define CDIM 128
#define NPIX (BATCH * IMH * IMW)   // 16384
#define NHEADS 4
#define HD 32
#define NBK 7
#define HID 512

// Scratch (device globals — no allocation allowed)
__device__ __nv_bfloat16 g_xn[NPIX * CDIM];        // LN1 out
__device__ __nv_bfloat16 g_qkv[NPIX * 3 * CDIM];   // qkv bf16
__device__ __nv_bfloat16 g_attn[NPIX * CDIM];      // attn out
__device__ float g_h[NPIX * CDIM];                 // residual 1 (fp32)
__device__ __nv_bfloat16 g_y[NPIX * CDIM];         // LN2 out
__device__ __nv_bfloat16 g_mlp[NPIX * HID];        // fc1+gelu out
// bf16 transposed weights: BT[n][k] = W[k][n]
__device__ __nv_bfloat16 g_wqkvT[384 * 128];
__device__ __nv_bfloat16 g_wprojT[128 * 128];
__device__ __nv_bfloat16 g_wfc1T[512 * 128];
__device__ __nv_bfloat16 g_wfc2T[128 * 512];

// ---------------------------------------------------------------------------
// PTX helpers (compute_103-safe)
// ---------------------------------------------------------------------------
__device__ __forceinline__ uint32_t smem_u32(const void* p) {
    uint32_t a;
    asm("{ .reg .u64 t; cvta.to.shared.u64 t, %1; cvt.u32.u64 %0, t; }"
        : "=r"(a) : "l"(p));
    return a;
}
__device__ __forceinline__ void ldm_x4(uint32_t* r, uint32_t addr) {
    asm volatile("ldmatrix.sync.aligned.m8n8.x4.shared.b16 {%0,%1,%2,%3}, [%4];"
                 : "=r"(r[0]), "=r"(r[1]), "=r"(r[2]), "=r"(r[3]) : "r"(addr));
}
__device__ __forceinline__ void ldm_x2(uint32_t* r, uint32_t addr) {
    asm volatile("ldmatrix.sync.aligned.m8n8.x2.shared.b16 {%0,%1}, [%2];"
                 : "=r"(r[0]), "=r"(r[1]) : "r"(addr));
}
__device__ __forceinline__ void mma_bf16(float* c, const uint32_t* a,
                                         const uint32_t* b) {
    asm volatile(
        "mma.sync.aligned.m16n8k16.row.col.f32.bf16.bf16.f32 "
        "{%0,%1,%2,%3}, {%4,%5,%6,%7}, {%8,%9}, {%0,%1,%2,%3};"
        : "+f"(c[0]), "+f"(c[1]), "+f"(c[2]), "+f"(c[3])
        : "r"(a[0]), "r"(a[1]), "r"(a[2]), "r"(a[3]), "r"(b[0]), "r"(b[1]));
}
__device__ __forceinline__ void cp_async16(uint32_t dst, const void* src) {
    asm volatile("cp.async.cg.shared.global [%0], [%1], 16;"
                 :: "r"(dst), "l"(src));
}
#define CP_COMMIT() asm volatile("cp.async.commit_group;")
#define CP_WAIT(n)  asm volatile("cp.async.wait_group %0;" :: "n"(n))

__device__ __forceinline__ float2 bf2f(uint32_t u) {
    float lo = __uint_as_float(u << 16);
    float hi = __uint_as_float(u & 0xffff0000u);
    return make_float2(lo, hi);
}

// ---------------------------------------------------------------------------
// Weight prep: transpose + convert to bf16
// ---------------------------------------------------------------------------
__global__ void prep_w_kernel(const float* __restrict__ qkv_w,
                              const float* __restrict__ proj_w,
                              const float* __restrict__ fc1_w,
                              const float* __restrict__ fc2_w) {
    int t = blockIdx.x * blockDim.x + threadIdx.x;
    if (t < 49152) {
        int n = t / 128, k = t % 128;
        g_wqkvT[t] = __float2bfloat16(qkv_w[k * 384 + n]);
        return;
    }
    t -= 49152;
    if (t < 16384) {
        int n = t / 128, k = t % 128;
        g_wprojT[t] = __float2bfloat16(proj_w[k * 128 + n]);
        return;
    }
    t -= 16384;
    if (t < 65536) {
        int n = t / 128, k = t % 128;
        g_wfc1T[t] = __float2bfloat16(fc1_w[k * 512 + n]);
        return;
    }
    t -= 65536;
    if (t < 65536) {
        int n = t / 512, k = t % 512;
        g_wfc2T[t] = __float2bfloat16(fc2_w[k * 128 + n]);
    }
}

// ---------------------------------------------------------------------------
// bf16 mma.sync GEMM + cp.async 2-stage pipeline (generic).
// Block 64x128, BK=32, 256 threads (8 warps: 2M x 4N), warp tile 32x32.
// epi: 0=bias, 1=bias+res, 2=bias+gelu.  obf: output bf16 (else fp32).
// ---------------------------------------------------------------------------
#define BMT 64
#define BNT 128
#define BKT 32
#define ASTR 40   // 40 bf16 = 80B row stride

__global__ void mma_gemm_kernel(const __nv_bfloat16* __restrict__ A,
                                const __nv_bfloat16* __restrict__ BT,
                                const float* __restrict__ bias,
                                const float* __restrict__ res,
                                void* __restrict__ Cv,
                                int N, int Kdim, int epi, int obf) {
    __shared__ __nv_bfloat16 As[2][BMT][ASTR];
    __shared__ __nv_bfloat16 Bs[2][BNT][ASTR];

    int tid = threadIdx.x;
    int wid = tid >> 5, lane = tid & 31;
    int warp_m = wid >> 2, warp_n = wid & 3;
    int m0 = blockIdx.y * BMT;
    int n0 = blockIdx.x * BNT;

    float acc[2][4][4] = {};

    int ldRow = tid >> 2, ldCh = tid & 3;
    const __nv_bfloat16* Ag  = A  + (long)(m0 + ldRow) * Kdim + ldCh * 8;
    const __nv_bfloat16* Bg0 = BT + (long)(n0 + ldRow) * Kdim + ldCh * 8;
    const __nv_bfloat16* Bg1 = BT + (long)(n0 + 64 + ldRow) * Kdim + ldCh * 8;
    uint32_t aDst = smem_u32(&As[0][ldRow][ldCh * 8]);
    uint32_t bDst0 = smem_u32(&Bs[0][ldRow][ldCh * 8]);
    uint32_t bDst1 = smem_u32(&Bs[0][64 + ldRow][ldCh * 8]);
    const uint32_t A_SS = BMT * ASTR * 2;
    const uint32_t B_SS = BNT * ASTR * 2;

    uint32_t aAddr[2], bAddr[4];
    #pragma unroll
    for (int mt = 0; mt < 2; mt++)
        aAddr[mt] = smem_u32(&As[0][warp_m * 32 + mt * 16 + (lane & 15)][(lane >> 4) * 8]);
    #pragma unroll
    for (int nt = 0; nt < 4; nt++)
        bAddr[nt] = smem_u32(&Bs[0][warp_n * 32 + nt * 8 + (lane & 7)][((lane >> 3) & 1) * 8]);

    int nc = Kdim >> 5;
    cp_async16(aDst, Ag);
    cp_async16(bDst0, Bg0);
    cp_async16(bDst1, Bg1);
    CP_COMMIT();

    for (int c = 0; c < nc; c++) {
        if (c + 1 < nc) {
            int kc = (c + 1) << 5;
            uint32_t s = ((c + 1) & 1);
            cp_async16(aDst + s * A_SS, Ag + kc);
            cp_async16(bDst0 + s * B_SS, Bg0 + kc);
            cp_async16(bDst1 + s * B_SS, Bg1 + kc);
            CP_COMMIT();
            CP_WAIT(1);
        } else {
            CP_WAIT(0);
        }
        __syncthreads();

        uint32_t sa = (c & 1) * A_SS, sb = (c & 1) * B_SS;
        #pragma unroll
        for (int ks = 0; ks < 2; ks++) {
            uint32_t af[2][4], bf[4][2];
            #pragma unroll
            for (int mt = 0; mt < 2; mt++)
                ldm_x4(af[mt], aAddr[mt] + sa + ks * 32);
            #pragma unroll
            for (int nt = 0; nt < 4; nt++)
                ldm_x2(bf[nt], bAddr[nt] + sb + ks * 32);
            #pragma unroll
            for (int mt = 0; mt < 2; mt++)
                #pragma unroll
                for (int nt = 0; nt < 4; nt++)
                    mma_bf16(acc[mt][nt], af[mt], bf[nt]);
        }
        __syncthreads();
    }

    int trow = lane >> 2, tcol = (lane & 3) * 2;
    #pragma unroll
    for (int mt = 0; mt < 2; mt++) {
        #pragma unroll
        for (int nt = 0; nt < 4; nt++) {
            int col = n0 + warp_n * 32 + nt * 8 + tcol;
            float b0 = bias[col], b1 = bias[col + 1];
            #pragma unroll
            for (int hh = 0; hh < 2; hh++) {
                int row = m0 + warp_m * 32 + mt * 16 + trow + hh * 8;
                float v0 = acc[mt][nt][hh * 2 + 0] + b0;
                float v1 = acc[mt][nt][hh * 2 + 1] + b1;
                if (epi == 1) {
                    float2 rv = *reinterpret_cast<const float2*>(
                        &res[(long)row * N + col]);
                    v0 += rv.x; v1 += rv.y;
                } else if (epi == 2) {
                    v0 = 0.5f * v0 * (1.0f + erff(v0 * 0.7071067811865476f));
                    v1 = 0.5f * v1 * (1.0f + erff(v1 * 0.7071067811865476f));
                }
                if (obf) {
                    __nv_bfloat162 p = __float22bfloat162_rn(make_float2(v0, v1));
                    *reinterpret_cast<uint32_t*>(
                        (__nv_bfloat16*)Cv + (long)row * N + col) =
                        *reinterpret_cast<uint32_t*>(&p);
                } else {
                    float2 ov = {v0, v1};
                    *reinterpret_cast<float2*>(
                        (float*)Cv + (long)row * N + col) = ov;
                }
            }
        }
    }
}

// ---------------------------------------------------------------------------
// Proj GEMM + residual + fused LN2. N=128=full row per block. Writes
// h (fp32, for FC2 residual) and y=LN2(h) (bf16).
// ---------------------------------------------------------------------------
__global__ void proj_ln_kernel(const __nv_bfloat16* __restrict__ A,
                               const __nv_bfloat16* __restrict__ BT,
                               const float* __restrict__ bias,
                               const float* __restrict__ res,
                               const float* __restrict__ g2,
                               const float* __restrict__ b2,
                               float* __restrict__ H,
                               __nv_bfloat16* __restrict__ Y) {
    const int N = 128, Kdim = 128;
    __shared__ __nv_bfloat16 As[2][BMT][ASTR];
    __shared__ __nv_bfloat16 Bs[2][BNT][ASTR];
    __shared__ float rsum[4][64], rsq[4][64];
    __shared__ float smean[64], srstd[64];

    int tid = threadIdx.x;
    int wid = tid >> 5, lane = tid & 31;
    int warp_m = wid >> 2, warp_n = wid & 3;
    int m0 = blockIdx.y * BMT;

    float acc[2][4][4] = {};

    int ldRow = tid >> 2, ldCh = tid & 3;
    const __nv_bfloat16* Ag  = A  + (long)(m0 + ldRow) * Kdim + ldCh * 8;
    const __nv_bfloat16* Bg0 = BT + (long)ldRow * Kdim + ldCh * 8;
    const __nv_bfloat16* Bg1 = BT + (long)(64 + ldRow) * Kdim + ldCh * 8;
    uint32_t aDst = smem_u32(&As[0][ldRow][ldCh * 8]);
    uint32_t bDst0 = smem_u32(&Bs[0][ldRow][ldCh * 8]);
    uint32_t bDst1 = smem_u32(&Bs[0][64 + ldRow][ldCh * 8]);
    const uint32_t A_SS = BMT * ASTR * 2;
    const uint32_t B_SS = BNT * ASTR * 2;

    uint32_t aAddr[2], bAddr[4];
    #pragma unroll
    for (int mt = 0; mt < 2; mt++)
        aAddr[mt] = smem_u32(&As[0][warp_m * 32 + mt * 16 + (lane & 15)][(lane >> 4) * 8]);
    #pragma unroll
    for (int nt = 0; nt < 4; nt++)
        bAddr[nt] = smem_u32(&Bs[0][warp_n * 32 + nt * 8 + (lane & 7)][((lane >> 3) & 1) * 8]);

    cp_async16(aDst, Ag);
    cp_async16(bDst0, Bg0);
    cp_async16(bDst1, Bg1);
    CP_COMMIT();

    for (int c = 0; c < 4; c++) {
        if (c < 3) {
            int kc = (c + 1) << 5;
            uint32_t s = ((c + 1) & 1);
            cp_async16(aDst + s * A_SS, Ag + kc);
            cp_async16(bDst0 + s * B_SS, Bg0 + kc);
            cp_async16(bDst1 + s * B_SS, Bg1 + kc);
            CP_COMMIT();
            CP_WAIT(1);
        } else {
            CP_WAIT(0);
        }
        __syncthreads();

        uint32_t sa = (c & 1) * A_SS, sb = (c & 1) * B_SS;
        #pragma unroll
        for (int ks = 0; ks < 2; ks++) {
            uint32_t af[2][4], bf[4][2];
            #pragma unroll
            for (int mt = 0; mt < 2; mt++)
                ldm_x4(af[mt], aAddr[mt] + sa + ks * 32);
            #pragma unroll
            for (int nt = 0; nt < 4; nt++)
                ldm_x2(bf[nt], bAddr[nt] + sb + ks * 32);
            #pragma unroll
            for (int mt = 0; mt < 2; mt++)
                #pragma unroll
                for (int nt = 0; nt < 4; nt++)
                    mma_bf16(acc[mt][nt], af[mt], bf[nt]);
        }
        __syncthreads();
    }

    int trow = lane >> 2, tcol = (lane & 3) * 2;
    float vals[2][4][2][2];
    #pragma unroll
    for (int mt = 0; mt < 2; mt++) {
        #pragma unroll
        for (int nt = 0; nt < 4; nt++) {
            int col = warp_n * 32 + nt * 8 + tcol;
            float b0 = bias[col], b1 = bias[col + 1];
            #pragma unroll
            for (int hh = 0; hh < 2; hh++) {
                int row = m0 + warp_m * 32 + mt * 16 + trow + hh * 8;
                float2 rv = *reinterpret_cast<const float2*>(&res[(long)row * N + col]);
                vals[mt][nt][hh][0] = acc[mt][nt][hh * 2 + 0] + b0 + rv.x;
                vals[mt][nt][hh][1] = acc[mt][nt][hh * 2 + 1] + b1 + rv.y;
            }
        }
    }
    #pragma unroll
    for (int mt = 0; mt < 2; mt++) {
        #pragma unroll
        for (int hh = 0; hh < 2; hh++) {
            float s = 0.0f, sq = 0.0f;
            #pragma unroll
            for (int nt = 0; nt < 4; nt++) {
                float a = vals[mt][nt][hh][0], bb = vals[mt][nt][hh][1];
                s += a + bb;
                sq += a * a + bb * bb;
            }
            s  += __shfl_xor_sync(0xffffffffu, s, 1);
            s  += __shfl_xor_sync(0xffffffffu, s, 2);
            sq += __shfl_xor_sync(0xffffffffu, sq, 1);
            sq += __shfl_xor_sync(0xffffffffu, sq, 2);
            if ((lane & 3) == 0) {
                int lr = warp_m * 32 + mt * 16 + trow + hh * 8;
                rsum[warp_n][lr] = s;
                rsq[warp_n][lr] = sq;
            }
        }
    }
    __syncthreads();
    if (tid < 64) {
        float su = rsum[0][tid] + rsum[1][tid] + rsum[2][tid] + rsum[3][tid];
        float sq = rsq[0][tid] + rsq[1][tid] + rsq[2][tid] + rsq[3][tid];
        float mean = su * (1.0f / 128.0f);
        float var = sq * (1.0f / 128.0f) - mean * mean;
        smean[tid] = mean;
        srstd[tid] = rsqrtf(var + 1e-5f);
    }
    __syncthreads();

    #pragma unroll
    for (int mt = 0; mt < 2; mt++) {
        #pragma unroll
        for (int nt = 0; nt < 4; nt++) {
            int col = warp_n * 32 + nt * 8 + tcol;
            float gg0 = g2[col], gg1 = g2[col + 1];
            float bb0 = b2[col], bb1 = b2[col + 1];
            #pragma unroll
            for (int hh = 0; hh < 2; hh++) {
                int lr = warp_m * 32 + mt * 16 + trow + hh * 8;
                int row = m0 + lr;
                float v0 = vals[mt][nt][hh][0], v1 = vals[mt][nt][hh][1];
                float2 hv = {v0, v1};
                *reinterpret_cast<float2*>(&H[(long)row * N + col]) = hv;
                float m = smean[lr], r = srstd[lr];
                float y0 = (v0 - m) * r * gg0 + bb0;
                float y1 = (v1 - m) * r * gg1 + bb1;
                __nv_bfloat162 p = __float22bfloat162_rn(make_float2(y0, y1));
                *reinterpret_cast<uint32_t*>(Y + (long)row * N + col) =
                    *reinterpret_cast<uint32_t*>(&p);
            }
        }
    }
}

// ---------------------------------------------------------------------------
// LayerNorm (LN1) -> bf16 out
// ---------------------------------------------------------------------------
__global__ void ln_kernel(const float* __restrict__ x,
                          const float* __restrict__ gamma,
                          const float* __restrict__ beta,
                          __nv_bfloat16* __restrict__ out) {
    int row = blockIdx.x;
    int t = threadIdx.x;
    float v = x[row * CDIM + t];

    __shared__ float s1[4], s2[4];
    int lane = t & 31, warp = t >> 5;

    float ws = v;
    #pragma unroll
    for (int off = 16; off; off >>= 1) ws += __shfl_xor_sync(0xffffffffu, ws, off);
    if (lane == 0) s1[warp] = ws;
    __syncthreads();
    float mean = (s1[0] + s1[1] + s1[2] + s1[3]) * (1.0f / CDIM);

    float d = v - mean;
    float ws2 = d * d;
    #pragma unroll
    for (int off = 16; off; off >>= 1) ws2 += __shfl_xor_sync(0xffffffffu, ws2, off);
    if (lane == 0) s2[warp] = ws2;
    __syncthreads();
    float var = (s2[0] + s2[1] + s2[2] + s2[3]) * (1.0f / CDIM);

    out[row * CDIM + t] =
        __float2bfloat16(d * rsqrtf(var + 1e-5f) * gamma[t] + beta[t]);
}

// ---------------------------------------------------------------------------
// Fully fused neighborhood attention. Block = (by, h). 256 threads (8 warps).
// 1. qsum_h[32] = scale * sum_x q[by,x,h*32+..]
// 2. 448 score dots into SMEM
// 3. Phase A: per-pixel softmax weights (warp covers 8 pixels)
// 4. Phase B: lane = (pixel g=lane>>2, quarter i=lane&3); 8 channels/lane via
//    LDS.128 V loads; one STG.128 per lane.
// ---------------------------------------------------------------------------
__global__ void natt_kernel(const __nv_bfloat16* __restrict__ qkv,
                            const float* __restrict__ rpb,
                            __nv_bfloat16* __restrict__ out) {
    __shared__ uint32_t Vs[NBK * 64 * 16];      // 28672 B
    __shared__ float s_sc[NBK * 64];            // 1792 B
    __shared__ float rpb_s[169];                // 676 B
    __shared__ float wbuf[8][8][49];            // 12544 B
    __shared__ float qpart[8][HD];              // 1024 B
    __shared__ float qs[HD];                    // 128 B

    int blk = blockIdx.x;
    int by = blk >> 2, h = blk & 3;
    int b = by >> 6, y = by & 63;
    int sy = min(max(y - 3, 0), IMH - NBK);
    int tid = threadIdx.x;
    int wid = tid >> 5, lane = tid & 31;

    // --- qsum partial: thread = (x = tid>>2, dg = tid&3), 8 channels each
    {
        int x = tid >> 2, dg = tid & 3;
        uint4 u = *reinterpret_cast<const uint4*>(
            &qkv[((long)(by * 64 + x)) * 384 + h * HD + dg * 8]);
        float2 f0 = bf2f(u.x), f1 = bf2f(u.y), f2 = bf2f(u.z), f3 = bf2f(u.w);
        float v[8] = {f0.x, f0.y, f1.x, f1.y, f2.x, f2.y, f3.x, f3.y};
        #pragma unroll
        for (int i = 0; i < 8; i++) {
            v[i] += __shfl_xor_sync(0xffffffffu, v[i], 4);
            v[i] += __shfl_xor_sync(0xffffffffu, v[i], 8);
            v[i] += __shfl_xor_sync(0xffffffffu, v[i], 16);
        }
        if (lane < 4) {
            #pragma unroll
            for (int i = 0; i < 8; i++)
                qpart[wid][lane * 8 + i] = v[i];
        }
    }

    // --- Stage V: 7*64*4 uint4
    for (int i = tid; i < NBK * 64 * 4; i += 256) {
        int ky = i >> 8;
        int rem = i & 255;
        int col = rem >> 2, d8 = rem & 3;
        int np = (b * 64 + sy + ky) * 64 + col;
        uint4 u = *reinterpret_cast<const uint4*>(
            &qkv[(long)np * 384 + 2 * CDIM + h * HD + d8 * 8]);
        *reinterpret_cast<uint4*>(&Vs[((ky * 64 + col) << 4) + d8 * 4]) = u;
    }
    if (tid < 169) rpb_s[tid] = rpb[h * 169 + tid];
    __syncthreads();

    if (tid < HD) {
        float s = 0.0f;
        #pragma unroll
        for (int w = 0; w < 8; w++) s += qpart[w][tid];
        qs[tid] = s * 0.17677669529663687f;
    }
    __syncthreads();

    // --- Score dots: 448 dots, <=2 per thread
    #pragma unroll
    for (int rep = 0; rep < 2; rep++) {
        int d = rep * 256 + tid;
        if (d < NBK * 64) {
            int ky = d >> 6, nx = d & 63;
            const __nv_bfloat16* kb =
                qkv + ((long)((b * 64 + sy + ky) * 64 + nx)) * 384 + CDIM + h * HD;
            float acc = 0.0f;
            #pragma unroll
            for (int j = 0; j < 4; j++) {
                uint4 u = *reinterpret_cast<const uint4*>(kb + j * 8);
                float2 f0 = bf2f(u.x), f1 = bf2f(u.y), f2 = bf2f(u.z), f3 = bf2f(u.w);
                acc += f0.x * qs[j * 8 + 0] + f0.y * qs[j * 8 + 1]
                     + f1.x * qs[j * 8 + 2] + f1.y * qs[j * 8 + 3]
                     + f2.x * qs[j * 8 + 4] + f2.y * qs[j * 8 + 5]
                     + f3.x * qs[j * 8 + 6] + f3.y * qs[j * 8 + 7];
            }
            s_sc[d] = acc;
        }
    }
    __syncthreads();

    // --- Phase A: softmax weights for this warp's 8 pixels
    #pragma unroll 2
    for (int i = 0; i < 8; i++) {
        int x = wid * 8 + i;
        int sx = min(max(x - 3, 0), IMW - NBK);
        int ryo = (sy - y + 6) * 13 + (sx - x + 6);

        float s0, s1 = -1e30f;
        {
            int ky = lane / NBK, kx = lane - ky * NBK;
            s0 = s_sc[ky * 64 + sx + kx] + rpb_s[ryo + ky * 13 + kx];
        }
        if (lane < 17) {
            int n = lane + 32;
            int ky = n / NBK, kx = n - ky * NBK;
            s1 = s_sc[ky * 64 + sx + kx] + rpb_s[ryo + ky * 13 + kx];
        }
        float m = fmaxf(s0, s1);
        #pragma unroll
        for (int off = 16; off; off >>= 1)
            m = fmaxf(m, __shfl_xor_sync(0xffffffffu, m, off));
        float e0 = __expf(s0 - m);
        float e1 = (lane < 17) ? __expf(s1 - m) : 0.0f;
        float sum = e0 + e1;
        #pragma unroll
        for (int off = 16; off; off >>= 1)
            sum += __shfl_xor_sync(0xffffffffu, sum, off);
        float inv = 1.0f / sum;
        wbuf[wid][i][lane] = e0 * inv;
        if (lane < 17) wbuf[wid][i][lane + 32] = e1 * inv;
    }
    __syncwarp();

    // --- Phase B: lane = (g = lane>>2 pixel, i = lane&3 quarter of channels)
    int g = lane >> 2, qi = lane & 3;
    int x = wid * 8 + g;
    int sx = min(max(x - 3, 0), IMW - NBK);
    const float* wp = wbuf[wid][g];

    float a0 = 0.f, a1 = 0.f, a2 = 0.f, a3 = 0.f,
          a4 = 0.f, a5 = 0.f, a6 = 0.f, a7 = 0.f;
    #pragma unroll
    for (int n = 0; n < 49; n++) {
        int ky = n / NBK, kx = n - ky * NBK;
        float wv = wp[n];
        uint4 u = *reinterpret_cast<const uint4*>(
            &Vs[((ky * 64 + sx + kx) << 4) + qi * 4]);
        float2 f0 = bf2f(u.x), f1 = bf2f(u.y), f2 = bf2f(u.z), f3 = bf2f(u.w);
        a0 = fmaf(wv, f0.x, a0); a1 = fmaf(wv, f0.y, a1);
        a2 = fmaf(wv, f1.x, a2); a3 = fmaf(wv, f1.y, a3);
        a4 = fmaf(wv, f2.x, a4); a5 = fmaf(wv, f2.y, a5);
        a6 = fmaf(wv, f3.x, a6); a7 = fmaf(wv, f3.y, a7);
    }
    int p = (b * 64 + y) * 64 + x;
    __nv_bfloat162 p0 = __float22bfloat162_rn(make_float2(a0, a1));
    __nv_bfloat162 p1 = __float22bfloat162_rn(make_float2(a2, a3));
    __nv_bfloat162 p2 = __float22bfloat162_rn(make_float2(a4, a5));
    __nv_bfloat162 p3 = __float22bfloat162_rn(make_float2(a6, a7));
    uint4 ov;
    ov.x = *reinterpret_cast<uint32_t*>(&p0);
    ov.y = *reinterpret_cast<uint32_t*>(&p1);
    ov.z = *reinterpret_cast<uint32_t*>(&p2);
    ov.w = *reinterpret_cast<uint32_t*>(&p3);
    *reinterpret_cast<uint4*>(out + (long)p * CDIM + h * HD + qi * 8) = ov;
}

// ---------------------------------------------------------------------------
extern "C" void kernel_launch(void* const* d_in, const int* in_sizes, int n_in,
                              void* d_out, int out_size) {
    const float* x      = (const float*)d_in[0];
    const float* ln1_g  = (const float*)d_in[1];
    const float* ln1_b  = (const float*)d_in[2];
    const float* qkv_w  = (const float*)d_in[3];
    const float* qkv_b  = (const float*)d_in[4];
    const float* rpb    = (const float*)d_in[5];
    const float* proj_w = (const float*)d_in[6];
    const float* proj_b = (const float*)d_in[7];
    const float* ln2_g  = (const float*)d_in[8];
    const float* ln2_b  = (const float*)d_in[9];
    const float* fc1_w  = (const float*)d_in[10];
    const float* fc1_b  = (const float*)d_in[11];
    const float* fc2_w  = (const float*)d_in[12];
    const float* fc2_b  = (const float*)d_in[13];
    float* out = (float*)d_out;

    __nv_bfloat16 *xn, *qkvb, *attnb, *yb, *mlpb;
    float *hb;
    cudaGetSymbolAddress((void**)&xn,      g_xn);
    cudaGetSymbolAddress((void**)&qkvb,    g_qkv);
    cudaGetSymbolAddress((void**)&attnb,   g_attn);
    cudaGetSymbolAddress((void**)&hb,      g_h);
    cudaGetSymbolAddress((void**)&yb,      g_y);
    cudaGetSymbolAddress((void**)&mlpb,    g_mlp);
    __nv_bfloat16 *wqkvT, *wprojT, *wfc1T, *wfc2T;
    cudaGetSymbolAddress((void**)&wqkvT, g_wqkvT);
    cudaGetSymbolAddress((void**)&wprojT, g_wprojT);
    cudaGetSymbolAddress((void**)&wfc1T, g_wfc1T);
    cudaGetSymbolAddress((void**)&wfc2T, g_wfc2T);

    // 0. Weight prep
    prep_w_kernel<<<768, 256>>>(qkv_w, proj_w, fc1_w, fc2_w);
    // 1. LN1 -> bf16
    ln_kernel<<<NPIX, CDIM>>>(x, ln1_g, ln1_b, xn);
    // 2. QKV GEMM -> bf16 qkv
    mma_gemm_kernel<<<dim3(3, 256), 256>>>(xn, wqkvT, qkv_b, nullptr,
                                           qkvb, 384, 128, 0, 1);
    // 3. Fused neighborhood attention
    natt_kernel<<<BATCH * IMH * NHEADS, 256>>>(qkvb, rpb, attnb);
    // 4. Proj GEMM + residual(x) + LN2 -> h (fp32) & y (bf16)
    proj_ln_kernel<<<dim3(1, 256), 256>>>(attnb, wprojT, proj_b, x,
                                          ln2_g, ln2_b, hb, yb);
    // 5. FC1 GEMM + GELU (bf16 out)
    mma_gemm_kernel<<<dim3(4, 256), 256>>>(yb, wfc1T, fc1_b, nullptr,
                                           mlpb, 512, 128, 2, 1);
    // 6. FC2 GEMM + residual(h) -> out (fp32)
    mma_gemm_kernel<<<dim3(1, 256), 256>>>(mlpb, wfc2T, fc2_b, hb,
                                           out, 128, 512, 1, 0);
}